// round 9
// baseline (speedup 1.0000x reference)
#include <cuda_runtime.h>
#include <cuda_bf16.h>
#include <cstdint>

// ---------------- device scratch (no allocations allowed) ----------------
__device__ __align__(16) __nv_bfloat16 g_ag1[256 * 1024 * 64];    // L1 input (squeezed L0 out) bf16, ci pad 64
__device__ __align__(16) float g_af1[256 * 1024 * 64];            // same, fp32 (center add)
__device__ __align__(16) __nv_bfloat16 g_w1[9 * 64 * 64];         // L1 residual weights (K1 - I) bf16, padded
__device__ __align__(16) __nv_bfloat16 g_xg[256 * 256 * 192];     // L2 input bf16 [b][p][ci]
__device__ __align__(16) float g_xf32[256 * 256 * 192];           // same, fp32
__device__ __align__(16) __nv_bfloat16 g_w2[9 * 3 * 192 * 64];    // L2 residual weights (K2 - I) bf16
__device__ float g_tld[256];
__device__ float g_scalar;

#define X_ELEMS (256 * 192 * 16 * 16)

// ---------------- packed f32x2 helpers ----------------
__device__ __forceinline__ void ffma2(unsigned long long& d, unsigned long long a,
                                      unsigned long long b) {
    asm("fma.rn.f32x2 %0, %1, %2, %0;" : "+l"(d) : "l"(a), "l"(b));
}
__device__ __forceinline__ float2 up2(unsigned long long v) {
    float2 f;
    asm("mov.b64 {%0,%1}, %2;" : "=f"(f.x), "=f"(f.y) : "l"(v));
    return f;
}
__device__ __forceinline__ float wred(float v) {
    #pragma unroll
    for (int o = 16; o; o >>= 1) v += __shfl_xor_sync(0xffffffffu, v, o);
    return v;
}

// ---------------- PTX helpers ----------------
__device__ __forceinline__ uint32_t smem_u32(const void* p) {
    uint32_t a;
    asm("{ .reg .u64 t; cvta.to.shared.u64 t, %1; cvt.u32.u64 %0, t; }" : "=r"(a) : "l"(p));
    return a;
}
__device__ __forceinline__ void cpasync16(uint32_t dst, const void* src) {
    asm volatile("cp.async.cg.shared.global [%0], [%1], 16;" :: "r"(dst), "l"(src));
}
__device__ __forceinline__ void cpasync_commit() {
    asm volatile("cp.async.commit_group;" ::: "memory");
}
template <int N>
__device__ __forceinline__ void cpasync_wait() {
    asm volatile("cp.async.wait_group %0;" :: "n"(N) : "memory");
}
__device__ __forceinline__ void ldsm4(uint32_t* r, uint32_t addr) {
    asm volatile("ldmatrix.sync.aligned.m8n8.x4.shared.b16 {%0,%1,%2,%3}, [%4];"
                 : "=r"(r[0]), "=r"(r[1]), "=r"(r[2]), "=r"(r[3]) : "r"(addr));
}
__device__ __forceinline__ void mma16816(float* d, const uint32_t* a, const uint32_t* b) {
    asm volatile(
        "mma.sync.aligned.m16n8k16.row.col.f32.bf16.bf16.f32 "
        "{%0,%1,%2,%3}, {%4,%5,%6,%7}, {%8,%9}, {%0,%1,%2,%3};"
        : "+f"(d[0]), "+f"(d[1]), "+f"(d[2]), "+f"(d[3])
        : "r"(a[0]), "r"(a[1]), "r"(a[2]), "r"(a[3]), "r"(b[0]), "r"(b[1]));
}
__device__ __forceinline__ uint32_t swz(uint32_t off) { return off ^ ((off >> 3) & 0x70); }

// ---------------- init / finalize ----------------
__global__ void init_kernel() {
    int t = threadIdx.x;
    g_tld[t] = 0.f;
    if (t == 0) g_scalar = 0.f;
}
// zero padding lanes ci 48..63 of ag1 (avoid NaN garbage entering MMA)
__global__ void zero_pad_ag1() {
    int idx = blockIdx.x * 256 + threadIdx.x;
    if (idx < 256 * 1024) {
        uint4 z = make_uint4(0, 0, 0, 0);
        *(uint4*)(g_ag1 + (size_t)idx * 64 + 48) = z;
        *(uint4*)(g_ag1 + (size_t)idx * 64 + 56) = z;
    }
}
__global__ void fin_kernel(float* __restrict__ out) {
    int t = threadIdx.x;
    out[X_ELEMS + t] = g_scalar + g_tld[t];
}

// ---------------- weight prep ----------------
__global__ void prep_w2(const float* __restrict__ K2) {
    int idx = blockIdx.x * 256 + threadIdx.x;
    if (idx >= 9 * 3 * 192 * 64) return;
    int cil = idx & 63;
    int r = idx >> 6;
    int co = r % 192;
    int q = r / 192;
    int cc = q % 3;
    int tap = q / 3;
    int ci = cc * 64 + cil;
    float w = K2[((size_t)co * 192 + ci) * 9 + tap];
    if (tap == 4 && ci == co) w -= 1.0f;
    g_w2[idx] = __float2bfloat16(w);
}
// g_w1[tap][co(64)][cil(64)] = K1[co][ci][tap] - I, zero outside 48x48
__global__ void prep_w1(const float* __restrict__ K1) {
    int idx = blockIdx.x * 256 + threadIdx.x;
    if (idx >= 9 * 64 * 64) return;
    int cil = idx & 63;
    int r = idx >> 6;
    int co = r % 64;
    int tap = r / 64;
    float w = 0.f;
    if (co < 48 && cil < 48) {
        w = K1[((size_t)co * 48 + cil) * 9 + tap];
        if (tap == 4 && cil == co) w -= 1.0f;
    }
    g_w1[idx] = __float2bfloat16(w);
}

// ---------------- scalar logdet (verified) ----------------
__device__ __forceinline__ float2 cmul(float2 a, float2 b) {
    return make_float2(a.x * b.x - a.y * b.y, a.x * b.y + a.y * b.x);
}

__global__ void logdet_kernel(const float* __restrict__ K0, const float* __restrict__ a0,
                              const float* __restrict__ K1, const float* __restrict__ a1,
                              const float* __restrict__ K2, const float* __restrict__ a2) {
    const int L = blockIdx.x;
    const float* K = (L == 0) ? K0 : ((L == 1) ? K1 : K2);
    const float* als = (L == 0) ? a0 : ((L == 1) ? a1 : a2);
    const int c = (L == 0) ? 12 : ((L == 1) ? 48 : 192);
    const int n = (L == 0) ? 64 : ((L == 1) ? 32 : 16);

    __shared__ float sh_t[9];
    __shared__ float shS[81];
    __shared__ float red[16];
    const int tid = threadIdx.x;
    if (tid < 9) sh_t[tid] = 0.f;
    if (tid < 81) shS[tid] = 0.f;
    __syncthreads();

    float a81[81];
    float t9[9];
    #pragma unroll
    for (int k = 0; k < 81; k++) a81[k] = 0.f;
    #pragma unroll
    for (int k = 0; k < 9; k++) t9[k] = 0.f;

    for (int idx = tid; idx < c * c; idx += 256) {
        int i = idx / c, j = idx - i * c;
        const float* Ka = K + (size_t)(i * c + j) * 9;
        const float* Kb = K + (size_t)(j * c + i) * 9;
        float av[9], bv[9];
        #pragma unroll
        for (int a = 0; a < 9; a++) { av[a] = Ka[a]; bv[a] = Kb[a]; }
        #pragma unroll
        for (int a = 0; a < 9; a++)
            #pragma unroll
            for (int b = 0; b < 9; b++) a81[a * 9 + b] += av[a] * bv[b];
        if (i == j) {
            #pragma unroll
            for (int a = 0; a < 9; a++) t9[a] += av[a];
        }
    }
    #pragma unroll
    for (int k = 0; k < 81; k++) atomicAdd(&shS[k], a81[k]);
    #pragma unroll
    for (int k = 0; k < 9; k++) atomicAdd(&sh_t[k], t9[k]);
    __syncthreads();

    float part = 0.f;
    for (int f = tid; f < n * n; f += 256) {
        int u = f / n, v = f - u * n;
        float su, cu, sv, cv;
        sincosf(-6.283185307179586f * (float)u / (float)n, &su, &cu);
        sincosf(-6.283185307179586f * (float)v / (float)n, &sv, &cv);
        float2 eu = make_float2(cu, su), ev = make_float2(cv, sv);
        float2 pU[3] = {make_float2(1.f, 0.f), eu, cmul(eu, eu)};
        float2 pV[3] = {make_float2(1.f, 0.f), ev, cmul(ev, ev)};
        float2 ph[9];
        #pragma unroll
        for (int dy = 0; dy < 3; dy++)
            #pragma unroll
            for (int dx = 0; dx < 3; dx++) ph[dy * 3 + dx] = cmul(pU[dy], pV[dx]);

        float2 T = make_float2(0.f, 0.f), T2 = make_float2(0.f, 0.f);
        #pragma unroll
        for (int a = 0; a < 9; a++) {
            T.x += sh_t[a] * ph[a].x;
            T.y += sh_t[a] * ph[a].y;
        }
        #pragma unroll
        for (int a = 0; a < 9; a++) {
            float2 inner = make_float2(0.f, 0.f);
            #pragma unroll
            for (int b = 0; b < 9; b++) {
                float s = shS[a * 9 + b];
                inner.x += s * ph[b].x;
                inner.y += s * ph[b].y;
            }
            float2 pi = cmul(ph[a], inner);
            T2.x += pi.x;
            T2.y += pi.y;
        }
        float2 e1 = cmul(pU[1], pV[1]);
        e1.y = -e1.y;
        float2 e2 = cmul(e1, e1);
        float A = e1.x * T.x - e1.y * T.y;
        float B = e2.x * T2.x - e2.y * T2.y;
        part += 2.f * A - 1.5f * (float)c - 0.5f * B;
    }

    float as = 0.f;
    for (int k = tid; k < c; k += 256) as += als[k];

    float w1 = wred(part);
    float w2 = wred(as);
    int wid = tid >> 5;
    if ((tid & 31) == 0) { red[wid] = w1; red[wid + 8] = w2; }
    __syncthreads();
    if (tid == 0) {
        float s1 = 0.f, s2 = 0.f;
        #pragma unroll
        for (int w = 0; w < 8; w++) { s1 += red[w]; s2 += red[w + 8]; }
        atomicAdd(&g_scalar, s1 + (float)(n * n) * s2);
    }
}

// ---------------- layer 0: fused FFMA conv (CIN=12 too small for HMMA) --------
// Writes output directly in L1's GEMM layout: bf16 ag1 + fp32 af1,
// index ((b * 1024 + y*32 + x) * 64 + g*12 + o), tanh'd.
template <int CPREV, int N, int CI_CHUNK, int OUT_BLK, int CIPAD>
__global__ void __launch_bounds__(256, 2)
conv_layer0(const float* __restrict__ X, const float* __restrict__ Kw,
            const float* __restrict__ cb, const float* __restrict__ ab,
            const float* __restrict__ als, __nv_bfloat16* __restrict__ YB,
            float* __restrict__ YF) {
    constexpr int CIN = 4 * CPREV;
    constexpr int COUT = CIN;
    constexpr int H = 2 * N;
    constexpr int NW = N / 2;
    constexpr int S_FLOATS = CI_CHUNK * 324 * 4;
    extern __shared__ float smem[];
    float* S = smem;
    float2* KS = (float2*)(smem + S_FLOATS);
    float* sE = (float*)(KS + CI_CHUNK * 9 * OUT_BLK);
    float* sAb = sE + OUT_BLK;

    const int tid = threadIdx.x;
    const int bq = blockIdx.x;
    const int b0 = bq * 4;
    constexpr int TILES_X = N / 16;
    const int ty = (blockIdx.y / TILES_X) * 16;
    const int tx = (blockIdx.y % TILES_X) * 16;
    const int og = blockIdx.z * OUT_BLK;
    const int py = tid >> 4, px = tid & 15;

    if (tid < OUT_BLK) {
        sE[tid] = expf(als[og + tid]);
        sAb[tid] = ab[og + tid];
    }

    unsigned long long accA[OUT_BLK], accB[OUT_BLK];
    #pragma unroll
    for (int o = 0; o < OUT_BLK; o++) { accA[o] = 0ull; accB[o] = 0ull; }

    for (int ci0 = 0; ci0 < CIN; ci0 += CI_CHUNK) {
        __syncthreads();
        for (int idx = tid; idx < CI_CHUNK * 324; idx += 256) {
            int ci = idx / 324;
            int rem = idx - ci * 324;
            int yy = rem / 18, xx = rem - yy * 18;
            int cig = ci0 + ci;
            int g = cig / CPREV;
            int cc = cig - g * CPREV;
            int gy = ty + yy - 1;
            if (gy < 0) gy += N;
            if (gy >= N) gy -= N;
            int gx = tx + xx - 1;
            if (gx < 0) gx += N;
            if (gx >= N) gx -= N;
            int sy = 2 * gy + (g & 1);
            int sx = 2 * gx + ((g ^ (g >> 1)) & 1);
            size_t base = ((size_t)cc * H + sy) * H + sx;
            size_t bstr = (size_t)CPREV * H * H;
            float4 val;
            val.x = X[base + (size_t)(b0 + 0) * bstr];
            val.y = X[base + (size_t)(b0 + 1) * bstr];
            val.z = X[base + (size_t)(b0 + 2) * bstr];
            val.w = X[base + (size_t)(b0 + 3) * bstr];
            *(float4*)(S + idx * 4) = val;
        }
        for (int idx = tid; idx < CI_CHUNK * 9 * OUT_BLK; idx += 256) {
            int ci = idx / (9 * OUT_BLK);
            int rem = idx - ci * 9 * OUT_BLK;
            int tap = rem / OUT_BLK;
            int o = rem - tap * OUT_BLK;
            float k = Kw[((size_t)(og + o) * CIN + (ci0 + ci)) * 9 + tap];
            KS[idx] = make_float2(k, k);
        }
        __syncthreads();

        #pragma unroll 1
        for (int ci = 0; ci < CI_CHUNK; ci++) {
            const float* Sci = S + ci * 1296;
            const float2* Kci = KS + ci * 9 * OUT_BLK;
            #pragma unroll
            for (int tap = 0; tap < 9; tap++) {
                int dy = tap / 3, dx = tap - dy * 3;
                ulonglong2 v =
                    *(const ulonglong2*)(Sci + ((py + dy) * 18 + (px + dx)) * 4);
                #pragma unroll
                for (int o = 0; o < OUT_BLK; o += 2) {
                    ulonglong2 kk = *(const ulonglong2*)(Kci + tap * OUT_BLK + o);
                    ffma2(accA[o], kk.x, v.x);
                    ffma2(accB[o], kk.x, v.y);
                    ffma2(accA[o + 1], kk.y, v.x);
                    ffma2(accB[o + 1], kk.y, v.y);
                }
            }
        }
    }

    const int i = ty + py, j = tx + px;
    float ld[4] = {0.f, 0.f, 0.f, 0.f};

    // epilogue: tanh + write GEMM layout (bf16 + fp32)
    const int y = i >> 1, x = j >> 1;
    const int hs = i & 1, ws = j & 1;
    const int g = (hs == ws) ? hs : (2 + hs);
    const int cibase = g * COUT + og;
    #pragma unroll 1
    for (int o = 0; o < OUT_BLK; o += 2) {
        float e0 = sE[o], a0v = sAb[o];
        float e1 = sE[o + 1], a1v = sAb[o + 1];
        float c0v = cb[((size_t)(og + o) * N + i) * N + j];
        float c1v = cb[((size_t)(og + o + 1) * N + i) * N + j];
        float2 pA0 = up2(accA[o]), pB0 = up2(accB[o]);
        float2 pA1 = up2(accA[o + 1]), pB1 = up2(accB[o + 1]);
        float z0[4] = {pA0.x, pA0.y, pB0.x, pB0.y};
        float z1[4] = {pA1.x, pA1.y, pB1.x, pB1.y};
        #pragma unroll
        for (int nb = 0; nb < 4; nb++) {
            float t0 = tanhf((z0[nb] + c0v) * e0 + a0v);
            float t1 = tanhf((z1[nb] + c1v) * e1 + a1v);
            ld[nb] += log1pf(-t0 * t0) + log1pf(-t1 * t1);
            size_t xi = ((size_t)(b0 + nb) * (NW * NW) + y * NW + x) * CIPAD + cibase + o;
            __nv_bfloat162 pk;
            pk.x = __float2bfloat16(t0);
            pk.y = __float2bfloat16(t1);
            *(__nv_bfloat162*)(YB + xi) = pk;
            *(float2*)(YF + xi) = make_float2(t0, t1);
        }
    }

    #pragma unroll
    for (int nb = 0; nb < 4; nb++) ld[nb] = wred(ld[nb]);
    __syncthreads();
    float* red = S;
    if ((tid & 31) == 0) {
        int w = tid >> 5;
        red[w * 4 + 0] = ld[0];
        red[w * 4 + 1] = ld[1];
        red[w * 4 + 2] = ld[2];
        red[w * 4 + 3] = ld[3];
    }
    __syncthreads();
    if (tid < 4) {
        float s = 0.f;
        #pragma unroll
        for (int w = 0; w < 8; w++) s += red[w * 4 + tid];
        atomicAdd(&g_tld[b0 + tid], s);
    }
}

// ---------------- shared HMMA tile sizes ----------------
#define ACT_OFF(s) ((s) * 32768)            // 256 rows x 128 B
#define WT_OFF(s)  (65536 + (s) * 8192)     // 64 rows x 128 B
#define MMA_SMEM 81920

// ---------------- layer 1: HMMA residual conv + tanh epilogue ----------------
// D = E1 * a1 over 9 chunks (tap x 64ci, 48 real). Epilogue: fp32 center add,
// cb/actnorm/tanh/logdet, and writes L2's GEMM layouts (bf16 xg + fp32 xf).
__device__ __forceinline__ void l1_stage(uint32_t smem_base, int buf, int c,
                                         const __nv_bfloat16* __restrict__ ag,
                                         int b, int mt0, int tid) {
    int dy = c / 3 - 1, dx = c % 3 - 1;
    {
        int p = mt0 + tid;
        int y = p >> 5, x = p & 31;
        int ys = (y + dy) & 31, xs = (x + dx) & 31;
        const char* src = (const char*)(ag + ((size_t)b * 1024 + ys * 32 + xs) * 64);
        uint32_t rb = smem_base + ACT_OFF(buf);
        #pragma unroll
        for (int s = 0; s < 8; s++) {
            uint32_t off = (uint32_t)tid * 128 + s * 16;
            cpasync16(rb + swz(off), src + s * 16);
        }
    }
    if (tid < 64) {
        const char* src = (const char*)(g_w1 + ((size_t)c * 64 + tid) * 64);
        uint32_t ra = smem_base + WT_OFF(buf);
        #pragma unroll
        for (int s = 0; s < 8; s++) {
            uint32_t off = (uint32_t)tid * 128 + s * 16;
            cpasync16(ra + swz(off), src + s * 16);
        }
    }
    cpasync_commit();
}

__global__ void __launch_bounds__(256, 2)
l1_mma(const __nv_bfloat16* __restrict__ ag, const float* __restrict__ af,
       const float* __restrict__ cb, const float* __restrict__ ab,
       const float* __restrict__ als,
       __nv_bfloat16* __restrict__ xg, float* __restrict__ xf) {
    extern __shared__ char smc[];
    uint32_t smem_base = smem_u32(smc);
    const int tid = threadIdx.x;
    const int lane = tid & 31, wid = tid >> 5;
    const int b = blockIdx.x;
    const int mt0 = blockIdx.y * 256;
    const int m0 = (wid & 3) * 64;
    const int n0 = (wid >> 2) * 32;

    float d[4][4][4];
    #pragma unroll
    for (int mt = 0; mt < 4; mt++)
        #pragma unroll
        for (int nt = 0; nt < 4; nt++)
            #pragma unroll
            for (int r = 0; r < 4; r++) d[mt][nt][r] = 0.f;

    l1_stage(smem_base, 0, 0, ag, b, mt0, tid);
    #pragma unroll 1
    for (int c = 0; c < 9; c++) {
        int cur = c & 1;
        if (c + 1 < 9) {
            l1_stage(smem_base, 1 - cur, c + 1, ag, b, mt0, tid);
            cpasync_wait<1>();
        } else {
            cpasync_wait<0>();
        }
        __syncthreads();
        uint32_t actb = smem_base + ACT_OFF(cur);
        uint32_t wtb = smem_base + WT_OFF(cur);
        #pragma unroll
        for (int ks = 0; ks < 4; ks++) {
            uint32_t a[4][4];
            #pragma unroll
            for (int mt = 0; mt < 4; mt++) {
                uint32_t off =
                    (uint32_t)(m0 + mt * 16 + (lane & 15)) * 128 + ks * 32 + (lane >> 4) * 16;
                ldsm4(a[mt], actb + swz(off));
            }
            uint32_t bf[2][4];
            #pragma unroll
            for (int nh = 0; nh < 2; nh++) {
                uint32_t row = n0 + nh * 16 + (lane & 7) + ((lane >> 4) << 3);
                uint32_t off = row * 128 + ks * 32 + ((lane >> 3) & 1) * 16;
                ldsm4(bf[nh], wtb + swz(off));
            }
            #pragma unroll
            for (int mt = 0; mt < 4; mt++)
                #pragma unroll
                for (int nt = 0; nt < 4; nt++)
                    mma16816(d[mt][nt], a[mt], &bf[nt >> 1][(nt & 1) * 2]);
        }
        __syncthreads();
    }

    // epilogue: center add + cb + actnorm + tanh + logdet + write L2 layouts
    float ldsum = 0.f;
    #pragma unroll
    for (int nt = 0; nt < 4; nt++) {
        int co = n0 + nt * 8 + (lane & 3) * 2;
        if (co < 48) {
            float e0 = expf(als[co]), e1 = expf(als[co + 1]);
            float ab0 = ab[co], ab1 = ab[co + 1];
            #pragma unroll
            for (int mt = 0; mt < 4; mt++) {
                #pragma unroll
                for (int half = 0; half < 2; half++) {
                    int p = mt0 + m0 + mt * 16 + (lane >> 2) + half * 8;
                    const float* afp = af + ((size_t)b * 1024 + p) * 64;
                    float z0 = d[mt][nt][half * 2] + afp[co] + cb[(size_t)co * 1024 + p];
                    float z1 = d[mt][nt][half * 2 + 1] + afp[co + 1] +
                               cb[(size_t)(co + 1) * 1024 + p];
                    float t0 = tanhf(z0 * e0 + ab0);
                    float t1 = tanhf(z1 * e1 + ab1);
                    ldsum += log1pf(-t0 * t0) + log1pf(-t1 * t1);
                    int i = p >> 5, j = p & 31;
                    int y = i >> 1, x = j >> 1;
                    int hs = i & 1, ws = j & 1;
                    int g = (hs == ws) ? hs : (2 + hs);
                    size_t xi = ((size_t)b * 256 + y * 16 + x) * 192 + g * 48 + co;
                    __nv_bfloat162 pk;
                    pk.x = __float2bfloat16(t0);
                    pk.y = __float2bfloat16(t1);
                    *(__nv_bfloat162*)(xg + xi) = pk;
                    *(float2*)(xf + xi) = make_float2(t0, t1);
                }
            }
        }
    }
    ldsum = wred(ldsum);
    __shared__ float red[8];
    if (lane == 0) red[wid] = ldsum;
    __syncthreads();
    if (tid == 0) {
        float s = 0.f;
        #pragma unroll
        for (int w = 0; w < 8; w++) s += red[w];
        atomicAdd(&g_tld[b], s);
    }
}

// ---------------- layer 2: HMMA residual implicit-GEMM conv (verified) --------
__device__ __forceinline__ void l2_stage(uint32_t smem_base, int buf, int c,
                                         const __nv_bfloat16* __restrict__ xg,
                                         int b, int co0, int tid) {
    int tap = c / 3, cc = c - tap * 3;
    int dy = tap / 3 - 1, dx = tap % 3 - 1;
    {
        int y = tid >> 4, x = tid & 15;
        int ys = (y + dy) & 15, xs = (x + dx) & 15;
        const char* src =
            (const char*)(xg + (((size_t)b * 256 + ys * 16 + xs) * 192 + cc * 64));
        uint32_t rb = smem_base + ACT_OFF(buf);
        #pragma unroll
        for (int s = 0; s < 8; s++) {
            uint32_t off = (uint32_t)tid * 128 + s * 16;
            cpasync16(rb + swz(off), src + s * 16);
        }
    }
    if (tid < 64) {
        const char* src = (const char*)(g_w2 + ((size_t)c * 192 + co0 + tid) * 64);
        uint32_t ra = smem_base + WT_OFF(buf);
        #pragma unroll
        for (int s = 0; s < 8; s++) {
            uint32_t off = (uint32_t)tid * 128 + s * 16;
            cpasync16(ra + swz(off), src + s * 16);
        }
    }
    cpasync_commit();
}

__global__ void __launch_bounds__(256, 2)
l2_mma(const __nv_bfloat16* __restrict__ xg, const float* __restrict__ xf,
       const float* __restrict__ cb, const float* __restrict__ ab,
       const float* __restrict__ als, float* __restrict__ out) {
    extern __shared__ char smc[];
    uint32_t smem_base = smem_u32(smc);
    const int tid = threadIdx.x;
    const int lane = tid & 31, wid = tid >> 5;
    const int b = blockIdx.x;
    const int co0 = blockIdx.y * 64;
    const int m0 = (wid & 3) * 64;
    const int n0 = (wid >> 2) * 32;

    float d[4][4][4];
    #pragma unroll
    for (int mt = 0; mt < 4; mt++)
        #pragma unroll
        for (int nt = 0; nt < 4; nt++)
            #pragma unroll
            for (int r = 0; r < 4; r++) d[mt][nt][r] = 0.f;

    l2_stage(smem_base, 0, 0, xg, b, co0, tid);
    #pragma unroll 1
    for (int c = 0; c < 27; c++) {
        int cur = c & 1;
        if (c + 1 < 27) {
            l2_stage(smem_base, 1 - cur, c + 1, xg, b, co0, tid);
            cpasync_wait<1>();
        } else {
            cpasync_wait<0>();
        }
        __syncthreads();
        uint32_t actb = smem_base + ACT_OFF(cur);
        uint32_t wtb = smem_base + WT_OFF(cur);
        #pragma unroll
        for (int ks = 0; ks < 4; ks++) {
            uint32_t a[4][4];
            #pragma unroll
            for (int mt = 0; mt < 4; mt++) {
                uint32_t off =
                    (uint32_t)(m0 + mt * 16 + (lane & 15)) * 128 + ks * 32 + (lane >> 4) * 16;
                ldsm4(a[mt], actb + swz(off));
            }
            uint32_t bf[2][4];
            #pragma unroll
            for (int nh = 0; nh < 2; nh++) {
                uint32_t row = n0 + nh * 16 + (lane & 7) + ((lane >> 4) << 3);
                uint32_t off = row * 128 + ks * 32 + ((lane >> 3) & 1) * 16;
                ldsm4(bf[nh], wtb + swz(off));
            }
            #pragma unroll
            for (int mt = 0; mt < 4; mt++)
                #pragma unroll
                for (int nt = 0; nt < 4; nt++)
                    mma16816(d[mt][nt], a[mt], &bf[nt >> 1][(nt & 1) * 2]);
        }
        __syncthreads();
    }

    #pragma unroll
    for (int nt = 0; nt < 4; nt++) {
        int co = co0 + n0 + nt * 8 + (lane & 3) * 2;
        float e0 = expf(als[co]), e1 = expf(als[co + 1]);
        float ab0 = ab[co], ab1 = ab[co + 1];
        const float* cb0p = cb + (size_t)co * 256;
        const float* cb1p = cb + (size_t)(co + 1) * 256;
        float* o0p = out + ((size_t)b * 192 + co) * 256;
        float* o1p = out + ((size_t)b * 192 + co + 1) * 256;
        #pragma unroll
        for (int mt = 0; mt < 4; mt++) {
            int p = m0 + mt * 16 + (lane >> 2);
            const float* xf0 = xf + ((size_t)b * 256 + p) * 192;
            const float* xf8 = xf + ((size_t)b * 256 + p + 8) * 192;
            o0p[p] = (d[mt][nt][0] + xf0[co] + cb0p[p]) * e0 + ab0;
            o1p[p] = (d[mt][nt][1] + xf0[co + 1] + cb1p[p]) * e1 + ab1;
            o0p[p + 8] = (d[mt][nt][2] + xf8[co] + cb0p[p + 8]) * e0 + ab0;
            o1p[p + 8] = (d[mt][nt][3] + xf8[co + 1] + cb1p[p + 8]) * e1 + ab1;
        }
    }
}

// ---------------- launch ----------------
extern "C" void kernel_launch(void* const* d_in, const int* in_sizes, int n_in,
                              void* d_out, int out_size) {
    const float* x = (const float*)d_in[0];
    const float* k0 = (const float*)d_in[1];
    const float* cb0 = (const float*)d_in[2];
    const float* ab0 = (const float*)d_in[3];
    const float* als0 = (const float*)d_in[4];
    const float* k1 = (const float*)d_in[5];
    const float* cb1 = (const float*)d_in[6];
    const float* ab1 = (const float*)d_in[7];
    const float* als1 = (const float*)d_in[8];
    const float* k2 = (const float*)d_in[9];
    const float* cb2 = (const float*)d_in[10];
    const float* ab2 = (const float*)d_in[11];
    const float* als2 = (const float*)d_in[12];
    float* out = (float*)d_out;

    __nv_bfloat16 *ag1, *xg;
    float *af1, *xf;
    cudaGetSymbolAddress((void**)&ag1, g_ag1);
    cudaGetSymbolAddress((void**)&af1, g_af1);
    cudaGetSymbolAddress((void**)&xg, g_xg);
    cudaGetSymbolAddress((void**)&xf, g_xf32);

    const int SM0 = 12 * 324 * 4 * 4 + 12 * 9 * 12 * 8 + 12 * 2 * 4;
    cudaFuncSetAttribute((const void*)conv_layer0<3, 64, 12, 12, 64>,
                         cudaFuncAttributeMaxDynamicSharedMemorySize, SM0);
    cudaFuncSetAttribute((const void*)l1_mma,
                         cudaFuncAttributeMaxDynamicSharedMemorySize, MMA_SMEM);
    cudaFuncSetAttribute((const void*)l2_mma,
                         cudaFuncAttributeMaxDynamicSharedMemorySize, MMA_SMEM);

    init_kernel<<<1, 256>>>();
    zero_pad_ag1<<<1024, 256>>>();
    logdet_kernel<<<3, 256>>>(k0, als0, k1, als1, k2, als2);
    prep_w1<<<(9 * 64 * 64 + 255) / 256, 256>>>(k1);
    prep_w2<<<(9 * 3 * 192 * 64 + 255) / 256, 256>>>(k2);

    // layer 0: [256,3,128,128] -> GEMM layout ag1 bf16 + af1 fp32 (tanh'd)
    conv_layer0<3, 64, 12, 12, 64>
        <<<dim3(64, 16, 1), 256, SM0>>>(x, k0, cb0, ab0, als0, ag1, af1);
    // layer 1: HMMA residual + tanh -> xg bf16 + xf fp32 (L2 layout)
    l1_mma<<<dim3(256, 4), 256, MMA_SMEM>>>(ag1, af1, cb1, ab1, als1, xg, xf);
    // layer 2: HMMA residual + center add -> d_out
    l2_mma<<<dim3(256, 3), 256, MMA_SMEM>>>(xg, xf, cb2, ab2, als2, out);

    fin_kernel<<<1, 256>>>(out);
}

// round 10
// speedup vs baseline: 1.6365x; 1.6365x over previous
#include <cuda_runtime.h>
#include <cuda_bf16.h>
#include <cstdint>

// ---------------- device scratch (no allocations allowed) ----------------
__device__ __align__(16) float g_x1[256 * 12 * 64 * 64];          // L0 out, packed fp32 [bq][12][64][64][4]
__device__ __align__(16) __nv_bfloat16 g_ag1[256 * 1024 * 64];    // L0 out squeezed bf16 [b][p][ci(48,pad64)]
__device__ __align__(16) __nv_bfloat16 g_w1[9 * 64 * 64];         // L1 residual weights (K1 - I) bf16, padded
__device__ __align__(16) __nv_bfloat16 g_xg[256 * 256 * 192];     // L2 input bf16 [b][p][ci]
__device__ __align__(16) float g_xf32[256 * 256 * 192];           // same, fp32 (L2 center add)
__device__ __align__(16) __nv_bfloat16 g_w2[9 * 3 * 192 * 64];    // L2 residual weights (K2 - I) bf16
__device__ float g_tld[256];
__device__ float g_scalar;

#define X_ELEMS (256 * 192 * 16 * 16)

// ---------------- packed f32x2 helpers ----------------
__device__ __forceinline__ void ffma2(unsigned long long& d, unsigned long long a,
                                      unsigned long long b) {
    asm("fma.rn.f32x2 %0, %1, %2, %0;" : "+l"(d) : "l"(a), "l"(b));
}
__device__ __forceinline__ float2 up2(unsigned long long v) {
    float2 f;
    asm("mov.b64 {%0,%1}, %2;" : "=f"(f.x), "=f"(f.y) : "l"(v));
    return f;
}
__device__ __forceinline__ float wred(float v) {
    #pragma unroll
    for (int o = 16; o; o >>= 1) v += __shfl_xor_sync(0xffffffffu, v, o);
    return v;
}

// ---------------- PTX helpers ----------------
__device__ __forceinline__ uint32_t smem_u32(const void* p) {
    uint32_t a;
    asm("{ .reg .u64 t; cvta.to.shared.u64 t, %1; cvt.u32.u64 %0, t; }" : "=r"(a) : "l"(p));
    return a;
}
__device__ __forceinline__ void cpasync16(uint32_t dst, const void* src) {
    asm volatile("cp.async.cg.shared.global [%0], [%1], 16;" :: "r"(dst), "l"(src));
}
__device__ __forceinline__ void cpasync_commit() {
    asm volatile("cp.async.commit_group;" ::: "memory");
}
template <int N>
__device__ __forceinline__ void cpasync_wait() {
    asm volatile("cp.async.wait_group %0;" :: "n"(N) : "memory");
}
__device__ __forceinline__ void ldsm4(uint32_t* r, uint32_t addr) {
    asm volatile("ldmatrix.sync.aligned.m8n8.x4.shared.b16 {%0,%1,%2,%3}, [%4];"
                 : "=r"(r[0]), "=r"(r[1]), "=r"(r[2]), "=r"(r[3]) : "r"(addr));
}
__device__ __forceinline__ void mma16816(float* d, const uint32_t* a, const uint32_t* b) {
    asm volatile(
        "mma.sync.aligned.m16n8k16.row.col.f32.bf16.bf16.f32 "
        "{%0,%1,%2,%3}, {%4,%5,%6,%7}, {%8,%9}, {%0,%1,%2,%3};"
        : "+f"(d[0]), "+f"(d[1]), "+f"(d[2]), "+f"(d[3])
        : "r"(a[0]), "r"(a[1]), "r"(a[2]), "r"(a[3]), "r"(b[0]), "r"(b[1]));
}
__device__ __forceinline__ uint32_t swz(uint32_t off) { return off ^ ((off >> 3) & 0x70); }

// ---------------- init / finalize ----------------
__global__ void init_kernel() {
    int t = threadIdx.x;
    g_tld[t] = 0.f;
    if (t == 0) g_scalar = 0.f;
}
// zero padding lanes ci 48..63 of ag1 (avoid NaN garbage entering MMA)
__global__ void zero_pad_ag1() {
    int idx = blockIdx.x * 256 + threadIdx.x;
    if (idx < 256 * 1024) {
        uint4 z = make_uint4(0, 0, 0, 0);
        *(uint4*)(g_ag1 + (size_t)idx * 64 + 48) = z;
        *(uint4*)(g_ag1 + (size_t)idx * 64 + 56) = z;
    }
}
__global__ void fin_kernel(float* __restrict__ out) {
    int t = threadIdx.x;
    out[X_ELEMS + t] = g_scalar + g_tld[t];
}

// ---------------- weight prep ----------------
__global__ void prep_w2(const float* __restrict__ K2) {
    int idx = blockIdx.x * 256 + threadIdx.x;
    if (idx >= 9 * 3 * 192 * 64) return;
    int cil = idx & 63;
    int r = idx >> 6;
    int co = r % 192;
    int q = r / 192;
    int cc = q % 3;
    int tap = q / 3;
    int ci = cc * 64 + cil;
    float w = K2[((size_t)co * 192 + ci) * 9 + tap];
    if (tap == 4 && ci == co) w -= 1.0f;
    g_w2[idx] = __float2bfloat16(w);
}
// g_w1[tap][co(64)][cil(64)] = K1[co][ci][tap] - I, zero outside 48x48
__global__ void prep_w1(const float* __restrict__ K1) {
    int idx = blockIdx.x * 256 + threadIdx.x;
    if (idx >= 9 * 64 * 64) return;
    int cil = idx & 63;
    int r = idx >> 6;
    int co = r % 64;
    int tap = r / 64;
    float w = 0.f;
    if (co < 48 && cil < 48) {
        w = K1[((size_t)co * 48 + cil) * 9 + tap];
        if (tap == 4 && cil == co) w -= 1.0f;
    }
    g_w1[idx] = __float2bfloat16(w);
}

// ---------------- scalar logdet (verified) ----------------
__device__ __forceinline__ float2 cmul(float2 a, float2 b) {
    return make_float2(a.x * b.x - a.y * b.y, a.x * b.y + a.y * b.x);
}

__global__ void logdet_kernel(const float* __restrict__ K0, const float* __restrict__ a0,
                              const float* __restrict__ K1, const float* __restrict__ a1,
                              const float* __restrict__ K2, const float* __restrict__ a2) {
    const int L = blockIdx.x;
    const float* K = (L == 0) ? K0 : ((L == 1) ? K1 : K2);
    const float* als = (L == 0) ? a0 : ((L == 1) ? a1 : a2);
    const int c = (L == 0) ? 12 : ((L == 1) ? 48 : 192);
    const int n = (L == 0) ? 64 : ((L == 1) ? 32 : 16);

    __shared__ float sh_t[9];
    __shared__ float shS[81];
    __shared__ float red[16];
    const int tid = threadIdx.x;
    if (tid < 9) sh_t[tid] = 0.f;
    if (tid < 81) shS[tid] = 0.f;
    __syncthreads();

    float a81[81];
    float t9[9];
    #pragma unroll
    for (int k = 0; k < 81; k++) a81[k] = 0.f;
    #pragma unroll
    for (int k = 0; k < 9; k++) t9[k] = 0.f;

    for (int idx = tid; idx < c * c; idx += 256) {
        int i = idx / c, j = idx - i * c;
        const float* Ka = K + (size_t)(i * c + j) * 9;
        const float* Kb = K + (size_t)(j * c + i) * 9;
        float av[9], bv[9];
        #pragma unroll
        for (int a = 0; a < 9; a++) { av[a] = Ka[a]; bv[a] = Kb[a]; }
        #pragma unroll
        for (int a = 0; a < 9; a++)
            #pragma unroll
            for (int b = 0; b < 9; b++) a81[a * 9 + b] += av[a] * bv[b];
        if (i == j) {
            #pragma unroll
            for (int a = 0; a < 9; a++) t9[a] += av[a];
        }
    }
    #pragma unroll
    for (int k = 0; k < 81; k++) atomicAdd(&shS[k], a81[k]);
    #pragma unroll
    for (int k = 0; k < 9; k++) atomicAdd(&sh_t[k], t9[k]);
    __syncthreads();

    float part = 0.f;
    for (int f = tid; f < n * n; f += 256) {
        int u = f / n, v = f - u * n;
        float su, cu, sv, cv;
        sincosf(-6.283185307179586f * (float)u / (float)n, &su, &cu);
        sincosf(-6.283185307179586f * (float)v / (float)n, &sv, &cv);
        float2 eu = make_float2(cu, su), ev = make_float2(cv, sv);
        float2 pU[3] = {make_float2(1.f, 0.f), eu, cmul(eu, eu)};
        float2 pV[3] = {make_float2(1.f, 0.f), ev, cmul(ev, ev)};
        float2 ph[9];
        #pragma unroll
        for (int dy = 0; dy < 3; dy++)
            #pragma unroll
            for (int dx = 0; dx < 3; dx++) ph[dy * 3 + dx] = cmul(pU[dy], pV[dx]);

        float2 T = make_float2(0.f, 0.f), T2 = make_float2(0.f, 0.f);
        #pragma unroll
        for (int a = 0; a < 9; a++) {
            T.x += sh_t[a] * ph[a].x;
            T.y += sh_t[a] * ph[a].y;
        }
        #pragma unroll
        for (int a = 0; a < 9; a++) {
            float2 inner = make_float2(0.f, 0.f);
            #pragma unroll
            for (int b = 0; b < 9; b++) {
                float s = shS[a * 9 + b];
                inner.x += s * ph[b].x;
                inner.y += s * ph[b].y;
            }
            float2 pi = cmul(ph[a], inner);
            T2.x += pi.x;
            T2.y += pi.y;
        }
        float2 e1 = cmul(pU[1], pV[1]);
        e1.y = -e1.y;
        float2 e2 = cmul(e1, e1);
        float A = e1.x * T.x - e1.y * T.y;
        float B = e2.x * T2.x - e2.y * T2.y;
        part += 2.f * A - 1.5f * (float)c - 0.5f * B;
    }

    float as = 0.f;
    for (int k = tid; k < c; k += 256) as += als[k];

    float w1 = wred(part);
    float w2 = wred(as);
    int wid = tid >> 5;
    if ((tid & 31) == 0) { red[wid] = w1; red[wid + 8] = w2; }
    __syncthreads();
    if (tid == 0) {
        float s1 = 0.f, s2 = 0.f;
        #pragma unroll
        for (int w = 0; w < 8; w++) { s1 += red[w]; s2 += red[w + 8]; }
        atomicAdd(&g_scalar, s1 + (float)(n * n) * s2);
    }
}

// ---------------- layer 0: fused FFMA conv ----------------
// Outputs: packed fp32 x1 [bq][12][64][64][4] (coalesced float4, for L1 center add)
//          ag1 bf16 [b][p=1024][ci=g*12+o, pad 64] (batched 8B stores, for L1 MMA)
__global__ void __launch_bounds__(256, 2)
conv_layer0(const float* __restrict__ X, const float* __restrict__ Kw,
            const float* __restrict__ cb, const float* __restrict__ ab,
            const float* __restrict__ als, float* __restrict__ Y,
            __nv_bfloat16* __restrict__ YB) {
    constexpr int CPREV = 3, N = 64, CI_CHUNK = 12, OUT_BLK = 12;
    constexpr int CIN = 12, H = 128;
    constexpr int S_FLOATS = CI_CHUNK * 324 * 4;
    extern __shared__ float smem[];
    float* S = smem;
    float2* KS = (float2*)(smem + S_FLOATS);
    float* sE = (float*)(KS + CI_CHUNK * 9 * OUT_BLK);
    float* sAb = sE + OUT_BLK;

    const int tid = threadIdx.x;
    const int bq = blockIdx.x;
    const int b0 = bq * 4;
    constexpr int TILES_X = N / 16;
    const int ty = (blockIdx.y / TILES_X) * 16;
    const int tx = (blockIdx.y % TILES_X) * 16;
    const int py = tid >> 4, px = tid & 15;

    if (tid < OUT_BLK) {
        sE[tid] = expf(als[tid]);
        sAb[tid] = ab[tid];
    }

    unsigned long long accA[OUT_BLK], accB[OUT_BLK];
    #pragma unroll
    for (int o = 0; o < OUT_BLK; o++) { accA[o] = 0ull; accB[o] = 0ull; }

    {
        __syncthreads();
        for (int idx = tid; idx < CI_CHUNK * 324; idx += 256) {
            int ci = idx / 324;
            int rem = idx - ci * 324;
            int yy = rem / 18, xx = rem - yy * 18;
            int g = ci / CPREV;
            int cc = ci - g * CPREV;
            int gy = ty + yy - 1;
            if (gy < 0) gy += N;
            if (gy >= N) gy -= N;
            int gx = tx + xx - 1;
            if (gx < 0) gx += N;
            if (gx >= N) gx -= N;
            int sy = 2 * gy + (g & 1);
            int sx = 2 * gx + ((g ^ (g >> 1)) & 1);
            size_t base = ((size_t)cc * H + sy) * H + sx;
            size_t bstr = (size_t)CPREV * H * H;
            float4 val;
            val.x = X[base + (size_t)(b0 + 0) * bstr];
            val.y = X[base + (size_t)(b0 + 1) * bstr];
            val.z = X[base + (size_t)(b0 + 2) * bstr];
            val.w = X[base + (size_t)(b0 + 3) * bstr];
            *(float4*)(S + idx * 4) = val;
        }
        for (int idx = tid; idx < CI_CHUNK * 9 * OUT_BLK; idx += 256) {
            int ci = idx / (9 * OUT_BLK);
            int rem = idx - ci * 9 * OUT_BLK;
            int tap = rem / OUT_BLK;
            int o = rem - tap * OUT_BLK;
            float k = Kw[((size_t)o * CIN + ci) * 9 + tap];
            KS[idx] = make_float2(k, k);
        }
        __syncthreads();

        #pragma unroll 1
        for (int ci = 0; ci < CI_CHUNK; ci++) {
            const float* Sci = S + ci * 1296;
            const float2* Kci = KS + ci * 9 * OUT_BLK;
            #pragma unroll
            for (int tap = 0; tap < 9; tap++) {
                int dy = tap / 3, dx = tap - dy * 3;
                ulonglong2 v =
                    *(const ulonglong2*)(Sci + ((py + dy) * 18 + (px + dx)) * 4);
                #pragma unroll
                for (int o = 0; o < OUT_BLK; o += 2) {
                    ulonglong2 kk = *(const ulonglong2*)(Kci + tap * OUT_BLK + o);
                    ffma2(accA[o], kk.x, v.x);
                    ffma2(accB[o], kk.x, v.y);
                    ffma2(accA[o + 1], kk.y, v.x);
                    ffma2(accB[o + 1], kk.y, v.y);
                }
            }
        }
    }

    const int i = ty + py, j = tx + px;
    float ld[4] = {0.f, 0.f, 0.f, 0.f};
    uint32_t pk[6][4];  // bf16x2 per (o-pair, nb)

    #pragma unroll
    for (int o = 0; o < OUT_BLK; o += 2) {
        float e0 = sE[o], a0v = sAb[o];
        float e1 = sE[o + 1], a1v = sAb[o + 1];
        float c0v = cb[((size_t)o * N + i) * N + j];
        float c1v = cb[((size_t)(o + 1) * N + i) * N + j];
        float2 pA0 = up2(accA[o]), pB0 = up2(accB[o]);
        float2 pA1 = up2(accA[o + 1]), pB1 = up2(accB[o + 1]);
        float z0[4] = {pA0.x, pA0.y, pB0.x, pB0.y};
        float z1[4] = {pA1.x, pA1.y, pB1.x, pB1.y};
        float t0[4], t1[4];
        #pragma unroll
        for (int nb = 0; nb < 4; nb++) {
            t0[nb] = tanhf((z0[nb] + c0v) * e0 + a0v);
            t1[nb] = tanhf((z1[nb] + c1v) * e1 + a1v);
            ld[nb] += log1pf(-t0[nb] * t0[nb]) + log1pf(-t1[nb] * t1[nb]);
            __nv_bfloat162 p2;
            p2.x = __float2bfloat16(t0[nb]);
            p2.y = __float2bfloat16(t1[nb]);
            pk[o >> 1][nb] = *(uint32_t*)&p2;
        }
        // coalesced packed fp32 stores (float4 = 4 batches)
        *(float4*)(Y + ((((size_t)bq * 12 + o) * N + i) * N + j) * 4) =
            make_float4(t0[0], t0[1], t0[2], t0[3]);
        *(float4*)(Y + ((((size_t)bq * 12 + o + 1) * N + i) * N + j) * 4) =
            make_float4(t1[0], t1[1], t1[2], t1[3]);
    }

    // ag1 bf16: per batch, 12 channels = 24B contiguous -> 3 x 8B stores
    {
        const int y = i >> 1, x = j >> 1;
        const int hs = i & 1, ws = j & 1;
        const int g = (hs == ws) ? hs : (2 + hs);
        #pragma unroll
        for (int nb = 0; nb < 4; nb++) {
            size_t base = ((size_t)(b0 + nb) * 1024 + y * 32 + x) * 64 + g * 12;
            *(uint2*)(YB + base) = make_uint2(pk[0][nb], pk[1][nb]);
            *(uint2*)(YB + base + 4) = make_uint2(pk[2][nb], pk[3][nb]);
            *(uint2*)(YB + base + 8) = make_uint2(pk[4][nb], pk[5][nb]);
        }
    }

    #pragma unroll
    for (int nb = 0; nb < 4; nb++) ld[nb] = wred(ld[nb]);
    __syncthreads();
    float* red = S;
    if ((tid & 31) == 0) {
        int w = tid >> 5;
        red[w * 4 + 0] = ld[0];
        red[w * 4 + 1] = ld[1];
        red[w * 4 + 2] = ld[2];
        red[w * 4 + 3] = ld[3];
    }
    __syncthreads();
    if (tid < 4) {
        float s = 0.f;
        #pragma unroll
        for (int w = 0; w < 8; w++) s += red[w * 4 + tid];
        atomicAdd(&g_tld[b0 + tid], s);
    }
}

// ---------------- shared HMMA tile sizes ----------------
#define ACT_OFF(s) ((s) * 32768)            // 256 rows x 128 B
#define WT_OFF(s)  (65536 + (s) * 8192)     // 64 rows x 128 B
#define MMA_SMEM 81920

// ---------------- layer 1: HMMA residual conv + tanh epilogue ----------------
__device__ __forceinline__ void l1_stage(uint32_t smem_base, int buf, int c,
                                         const __nv_bfloat16* __restrict__ ag,
                                         int b, int mt0, int tid) {
    int dy = c / 3 - 1, dx = c % 3 - 1;
    {
        int p = mt0 + tid;
        int y = p >> 5, x = p & 31;
        int ys = (y + dy) & 31, xs = (x + dx) & 31;
        const char* src = (const char*)(ag + ((size_t)b * 1024 + ys * 32 + xs) * 64);
        uint32_t rb = smem_base + ACT_OFF(buf);
        #pragma unroll
        for (int s = 0; s < 8; s++) {
            uint32_t off = (uint32_t)tid * 128 + s * 16;
            cpasync16(rb + swz(off), src + s * 16);
        }
    }
    if (tid < 64) {
        const char* src = (const char*)(g_w1 + ((size_t)c * 64 + tid) * 64);
        uint32_t ra = smem_base + WT_OFF(buf);
        #pragma unroll
        for (int s = 0; s < 8; s++) {
            uint32_t off = (uint32_t)tid * 128 + s * 16;
            cpasync16(ra + swz(off), src + s * 16);
        }
    }
    cpasync_commit();
}

__global__ void __launch_bounds__(256, 2)
l1_mma(const __nv_bfloat16* __restrict__ ag, const float* __restrict__ x1p,
       const float* __restrict__ cb, const float* __restrict__ ab,
       const float* __restrict__ als,
       __nv_bfloat16* __restrict__ xg, float* __restrict__ xf) {
    extern __shared__ char smc[];
    uint32_t smem_base = smem_u32(smc);
    const int tid = threadIdx.x;
    const int lane = tid & 31, wid = tid >> 5;
    const int b = blockIdx.x;
    const int mt0 = blockIdx.y * 256;
    const int m0 = (wid & 3) * 64;
    const int n0 = (wid >> 2) * 32;
    const int bq = b >> 2, nb = b & 3;

    float d[4][4][4];
    #pragma unroll
    for (int mt = 0; mt < 4; mt++)
        #pragma unroll
        for (int nt = 0; nt < 4; nt++)
            #pragma unroll
            for (int r = 0; r < 4; r++) d[mt][nt][r] = 0.f;

    l1_stage(smem_base, 0, 0, ag, b, mt0, tid);
    #pragma unroll 1
    for (int c = 0; c < 9; c++) {
        int cur = c & 1;
        if (c + 1 < 9) {
            l1_stage(smem_base, 1 - cur, c + 1, ag, b, mt0, tid);
            cpasync_wait<1>();
        } else {
            cpasync_wait<0>();
        }
        __syncthreads();
        uint32_t actb = smem_base + ACT_OFF(cur);
        uint32_t wtb = smem_base + WT_OFF(cur);
        #pragma unroll
        for (int ks = 0; ks < 4; ks++) {
            uint32_t a[4][4];
            #pragma unroll
            for (int mt = 0; mt < 4; mt++) {
                uint32_t off =
                    (uint32_t)(m0 + mt * 16 + (lane & 15)) * 128 + ks * 32 + (lane >> 4) * 16;
                ldsm4(a[mt], actb + swz(off));
            }
            uint32_t bf[2][4];
            #pragma unroll
            for (int nh = 0; nh < 2; nh++) {
                uint32_t row = n0 + nh * 16 + (lane & 7) + ((lane >> 4) << 3);
                uint32_t off = row * 128 + ks * 32 + ((lane >> 3) & 1) * 16;
                ldsm4(bf[nh], wtb + swz(off));
            }
            #pragma unroll
            for (int mt = 0; mt < 4; mt++)
                #pragma unroll
                for (int nt = 0; nt < 4; nt++)
                    mma16816(d[mt][nt], a[mt], &bf[nt >> 1][(nt & 1) * 2]);
        }
        __syncthreads();
    }

    // epilogue: center add (from packed fp32 x1) + cb + actnorm + tanh + logdet
    float ldsum = 0.f;
    #pragma unroll
    for (int nt = 0; nt < 4; nt++) {
        int co = n0 + nt * 8 + (lane & 3) * 2;
        if (co < 48) {
            int g0 = co / 12, c0 = co - g0 * 12;
            int co1 = co + 1;
            int g1 = co1 / 12, c1 = co1 - g1 * 12;
            int hs0 = g0 & 1, ws0 = (g0 ^ (g0 >> 1)) & 1;
            int hs1 = g1 & 1, ws1 = (g1 ^ (g1 >> 1)) & 1;
            float e0 = expf(als[co]), e1 = expf(als[co1]);
            float ab0 = ab[co], ab1 = ab[co1];
            #pragma unroll
            for (int mt = 0; mt < 4; mt++) {
                #pragma unroll
                for (int half = 0; half < 2; half++) {
                    int p = mt0 + m0 + mt * 16 + (lane >> 2) + half * 8;
                    int i = p >> 5, j = p & 31;
                    float xc0 = x1p[((((size_t)bq * 12 + c0) * 64 + (2 * i + hs0)) * 64 +
                                     (2 * j + ws0)) * 4 + nb];
                    float xc1 = x1p[((((size_t)bq * 12 + c1) * 64 + (2 * i + hs1)) * 64 +
                                     (2 * j + ws1)) * 4 + nb];
                    float z0 = d[mt][nt][half * 2] + xc0 + cb[(size_t)co * 1024 + p];
                    float z1 = d[mt][nt][half * 2 + 1] + xc1 + cb[(size_t)co1 * 1024 + p];
                    float t0 = tanhf(z0 * e0 + ab0);
                    float t1 = tanhf(z1 * e1 + ab1);
                    ldsum += log1pf(-t0 * t0) + log1pf(-t1 * t1);
                    int y = i >> 1, x = j >> 1;
                    int hs = i & 1, ws = j & 1;
                    int g = (hs == ws) ? hs : (2 + hs);
                    size_t xi = ((size_t)b * 256 + y * 16 + x) * 192 + g * 48 + co;
                    __nv_bfloat162 pk2;
                    pk2.x = __float2bfloat16(t0);
                    pk2.y = __float2bfloat16(t1);
                    *(__nv_bfloat162*)(xg + xi) = pk2;
                    *(float2*)(xf + xi) = make_float2(t0, t1);
                }
            }
        }
    }
    ldsum = wred(ldsum);
    __shared__ float red[8];
    if (lane == 0) red[wid] = ldsum;
    __syncthreads();
    if (tid == 0) {
        float s = 0.f;
        #pragma unroll
        for (int w = 0; w < 8; w++) s += red[w];
        atomicAdd(&g_tld[b], s);
    }
}

// ---------------- layer 2: HMMA residual implicit-GEMM conv (verified) --------
__device__ __forceinline__ void l2_stage(uint32_t smem_base, int buf, int c,
                                         const __nv_bfloat16* __restrict__ xg,
                                         int b, int co0, int tid) {
    int tap = c / 3, cc = c - tap * 3;
    int dy = tap / 3 - 1, dx = tap % 3 - 1;
    {
        int y = tid >> 4, x = tid & 15;
        int ys = (y + dy) & 15, xs = (x + dx) & 15;
        const char* src =
            (const char*)(xg + (((size_t)b * 256 + ys * 16 + xs) * 192 + cc * 64));
        uint32_t rb = smem_base + ACT_OFF(buf);
        #pragma unroll
        for (int s = 0; s < 8; s++) {
            uint32_t off = (uint32_t)tid * 128 + s * 16;
            cpasync16(rb + swz(off), src + s * 16);
        }
    }
    if (tid < 64) {
        const char* src = (const char*)(g_w2 + ((size_t)c * 192 + co0 + tid) * 64);
        uint32_t ra = smem_base + WT_OFF(buf);
        #pragma unroll
        for (int s = 0; s < 8; s++) {
            uint32_t off = (uint32_t)tid * 128 + s * 16;
            cpasync16(ra + swz(off), src + s * 16);
        }
    }
    cpasync_commit();
}

__global__ void __launch_bounds__(256, 2)
l2_mma(const __nv_bfloat16* __restrict__ xg, const float* __restrict__ xf,
       const float* __restrict__ cb, const float* __restrict__ ab,
       const float* __restrict__ als, float* __restrict__ out) {
    extern __shared__ char smc[];
    uint32_t smem_base = smem_u32(smc);
    const int tid = threadIdx.x;
    const int lane = tid & 31, wid = tid >> 5;
    const int b = blockIdx.x;
    const int co0 = blockIdx.y * 64;
    const int m0 = (wid & 3) * 64;
    const int n0 = (wid >> 2) * 32;

    float d[4][4][4];
    #pragma unroll
    for (int mt = 0; mt < 4; mt++)
        #pragma unroll
        for (int nt = 0; nt < 4; nt++)
            #pragma unroll
            for (int r = 0; r < 4; r++) d[mt][nt][r] = 0.f;

    l2_stage(smem_base, 0, 0, xg, b, co0, tid);
    #pragma unroll 1
    for (int c = 0; c < 27; c++) {
        int cur = c & 1;
        if (c + 1 < 27) {
            l2_stage(smem_base, 1 - cur, c + 1, xg, b, co0, tid);
            cpasync_wait<1>();
        } else {
            cpasync_wait<0>();
        }
        __syncthreads();
        uint32_t actb = smem_base + ACT_OFF(cur);
        uint32_t wtb = smem_base + WT_OFF(cur);
        #pragma unroll
        for (int ks = 0; ks < 4; ks++) {
            uint32_t a[4][4];
            #pragma unroll
            for (int mt = 0; mt < 4; mt++) {
                uint32_t off =
                    (uint32_t)(m0 + mt * 16 + (lane & 15)) * 128 + ks * 32 + (lane >> 4) * 16;
                ldsm4(a[mt], actb + swz(off));
            }
            uint32_t bf[2][4];
            #pragma unroll
            for (int nh = 0; nh < 2; nh++) {
                uint32_t row = n0 + nh * 16 + (lane & 7) + ((lane >> 4) << 3);
                uint32_t off = row * 128 + ks * 32 + ((lane >> 3) & 1) * 16;
                ldsm4(bf[nh], wtb + swz(off));
            }
            #pragma unroll
            for (int mt = 0; mt < 4; mt++)
                #pragma unroll
                for (int nt = 0; nt < 4; nt++)
                    mma16816(d[mt][nt], a[mt], &bf[nt >> 1][(nt & 1) * 2]);
        }
        __syncthreads();
    }

    #pragma unroll
    for (int nt = 0; nt < 4; nt++) {
        int co = co0 + n0 + nt * 8 + (lane & 3) * 2;
        float e0 = expf(als[co]), e1 = expf(als[co + 1]);
        float ab0 = ab[co], ab1 = ab[co + 1];
        const float* cb0p = cb + (size_t)co * 256;
        const float* cb1p = cb + (size_t)(co + 1) * 256;
        float* o0p = out + ((size_t)b * 192 + co) * 256;
        float* o1p = out + ((size_t)b * 192 + co + 1) * 256;
        #pragma unroll
        for (int mt = 0; mt < 4; mt++) {
            int p = m0 + mt * 16 + (lane >> 2);
            const float* xf0 = xf + ((size_t)b * 256 + p) * 192;
            const float* xf8 = xf + ((size_t)b * 256 + p + 8) * 192;
            o0p[p] = (d[mt][nt][0] + xf0[co] + cb0p[p]) * e0 + ab0;
            o1p[p] = (d[mt][nt][1] + xf0[co + 1] + cb1p[p]) * e1 + ab1;
            o0p[p + 8] = (d[mt][nt][2] + xf8[co] + cb0p[p + 8]) * e0 + ab0;
            o1p[p + 8] = (d[mt][nt][3] + xf8[co + 1] + cb1p[p + 8]) * e1 + ab1;
        }
    }
}

// ---------------- launch ----------------
extern "C" void kernel_launch(void* const* d_in, const int* in_sizes, int n_in,
                              void* d_out, int out_size) {
    const float* x = (const float*)d_in[0];
    const float* k0 = (const float*)d_in[1];
    const float* cb0 = (const float*)d_in[2];
    const float* ab0 = (const float*)d_in[3];
    const float* als0 = (const float*)d_in[4];
    const float* k1 = (const float*)d_in[5];
    const float* cb1 = (const float*)d_in[6];
    const float* ab1 = (const float*)d_in[7];
    const float* als1 = (const float*)d_in[8];
    const float* k2 = (const float*)d_in[9];
    const float* cb2 = (const float*)d_in[10];
    const float* ab2 = (const float*)d_in[11];
    const float* als2 = (const float*)d_in[12];
    float* out = (float*)d_out;

    float *x1, *xf;
    __nv_bfloat16 *ag1, *xg;
    cudaGetSymbolAddress((void**)&x1, g_x1);
    cudaGetSymbolAddress((void**)&ag1, g_ag1);
    cudaGetSymbolAddress((void**)&xg, g_xg);
    cudaGetSymbolAddress((void**)&xf, g_xf32);

    const int SM0 = 12 * 324 * 4 * 4 + 12 * 9 * 12 * 8 + 12 * 2 * 4;
    cudaFuncSetAttribute((const void*)conv_layer0,
                         cudaFuncAttributeMaxDynamicSharedMemorySize, SM0);
    cudaFuncSetAttribute((const void*)l1_mma,
                         cudaFuncAttributeMaxDynamicSharedMemorySize, MMA_SMEM);
    cudaFuncSetAttribute((const void*)l2_mma,
                         cudaFuncAttributeMaxDynamicSharedMemorySize, MMA_SMEM);

    init_kernel<<<1, 256>>>();
    zero_pad_ag1<<<1024, 256>>>();
    logdet_kernel<<<3, 256>>>(k0, als0, k1, als1, k2, als2);
    prep_w1<<<(9 * 64 * 64 + 255) / 256, 256>>>(k1);
    prep_w2<<<(9 * 3 * 192 * 64 + 255) / 256, 256>>>(k2);

    // layer 0: FFMA conv -> packed fp32 x1 (coalesced) + bf16 ag1 (batched 8B)
    conv_layer0<<<dim3(64, 16, 1), 256, SM0>>>(x, k0, cb0, ab0, als0, x1, ag1);
    // layer 1: HMMA residual + center add from x1 -> xg bf16 + xf fp32
    l1_mma<<<dim3(256, 4), 256, MMA_SMEM>>>(ag1, x1, cb1, ab1, als1, xg, xf);
    // layer 2: HMMA residual + center add from xf -> d_out
    l2_mma<<<dim3(256, 3), 256, MMA_SMEM>>>(xg, xf, cb2, ab2, als2, out);

    fin_kernel<<<1, 256>>>(out);
}

// round 11
// speedup vs baseline: 2.0088x; 1.2275x over previous
#include <cuda_runtime.h>
#include <cuda_bf16.h>
#include <cstdint>

// ---------------- device scratch (no allocations allowed) ----------------
__device__ __align__(16) float g_x1[256 * 12 * 64 * 64];          // L0 out, packed fp32 [bq][12][64][64][4]
__device__ __align__(16) __nv_bfloat16 g_ag1[256 * 1024 * 64];    // L0 out squeezed bf16 [b][p][ci(48,pad64)]
__device__ __align__(16) __nv_bfloat16 g_w1[9 * 64 * 64];         // L1 residual weights (K1 - I) bf16, padded
__device__ __align__(16) __nv_bfloat16 g_xg[256 * 256 * 192];     // L2 input bf16 [b][p][ci]
__device__ __align__(16) float g_xf32[256 * 256 * 192];           // same, fp32 (L2 center add)
__device__ __align__(16) __nv_bfloat16 g_w2[9 * 3 * 192 * 64];    // L2 residual weights (K2 - I) bf16
__device__ float g_tld[256];
__device__ float g_scalar;

#define X_ELEMS (256 * 192 * 16 * 16)

// ---------------- packed f32x2 helpers ----------------
__device__ __forceinline__ void ffma2(unsigned long long& d, unsigned long long a,
                                      unsigned long long b) {
    asm("fma.rn.f32x2 %0, %1, %2, %0;" : "+l"(d) : "l"(a), "l"(b));
}
__device__ __forceinline__ float2 up2(unsigned long long v) {
    float2 f;
    asm("mov.b64 {%0,%1}, %2;" : "=f"(f.x), "=f"(f.y) : "l"(v));
    return f;
}
__device__ __forceinline__ float wred(float v) {
    #pragma unroll
    for (int o = 16; o; o >>= 1) v += __shfl_xor_sync(0xffffffffu, v, o);
    return v;
}

// ---------------- PTX helpers ----------------
__device__ __forceinline__ uint32_t smem_u32(const void* p) {
    uint32_t a;
    asm("{ .reg .u64 t; cvta.to.shared.u64 t, %1; cvt.u32.u64 %0, t; }" : "=r"(a) : "l"(p));
    return a;
}
__device__ __forceinline__ void cpasync16(uint32_t dst, const void* src) {
    asm volatile("cp.async.cg.shared.global [%0], [%1], 16;" :: "r"(dst), "l"(src));
}
__device__ __forceinline__ void cpasync_commit() {
    asm volatile("cp.async.commit_group;" ::: "memory");
}
template <int N>
__device__ __forceinline__ void cpasync_wait() {
    asm volatile("cp.async.wait_group %0;" :: "n"(N) : "memory");
}
__device__ __forceinline__ void ldsm4(uint32_t* r, uint32_t addr) {
    asm volatile("ldmatrix.sync.aligned.m8n8.x4.shared.b16 {%0,%1,%2,%3}, [%4];"
                 : "=r"(r[0]), "=r"(r[1]), "=r"(r[2]), "=r"(r[3]) : "r"(addr));
}
__device__ __forceinline__ void mma16816(float* d, const uint32_t* a, const uint32_t* b) {
    asm volatile(
        "mma.sync.aligned.m16n8k16.row.col.f32.bf16.bf16.f32 "
        "{%0,%1,%2,%3}, {%4,%5,%6,%7}, {%8,%9}, {%0,%1,%2,%3};"
        : "+f"(d[0]), "+f"(d[1]), "+f"(d[2]), "+f"(d[3])
        : "r"(a[0]), "r"(a[1]), "r"(a[2]), "r"(a[3]), "r"(b[0]), "r"(b[1]));
}
__device__ __forceinline__ uint32_t swz(uint32_t off) { return off ^ ((off >> 3) & 0x70); }

// ---------------- fused setup: init + zero_pad + prep_w1 + prep_w2 -----------
// blocks: [0] init, [1..1024] ag1 pad-zero, [1025..1168] w1, [1169..2464] w2
__global__ void setup_kernel(const float* __restrict__ K1, const float* __restrict__ K2) {
    int bid = blockIdx.x, tid = threadIdx.x;
    if (bid == 0) {
        g_tld[tid] = 0.f;
        if (tid == 0) g_scalar = 0.f;
    } else if (bid <= 1024) {
        int idx = (bid - 1) * 256 + tid;  // < 256*1024
        uint4 z = make_uint4(0, 0, 0, 0);
        *(uint4*)(g_ag1 + (size_t)idx * 64 + 48) = z;
        *(uint4*)(g_ag1 + (size_t)idx * 64 + 56) = z;
    } else if (bid <= 1168) {
        int idx = (bid - 1025) * 256 + tid;  // < 9*64*64
        int cil = idx & 63;
        int r = idx >> 6;
        int co = r % 64;
        int tap = r / 64;
        float w = 0.f;
        if (co < 48 && cil < 48) {
            w = K1[((size_t)co * 48 + cil) * 9 + tap];
            if (tap == 4 && cil == co) w -= 1.0f;
        }
        g_w1[idx] = __float2bfloat16(w);
    } else {
        int idx = (bid - 1169) * 256 + tid;  // < 9*3*192*64
        int cil = idx & 63;
        int r = idx >> 6;
        int co = r % 192;
        int q = r / 192;
        int cc = q % 3;
        int tap = q / 3;
        int ci = cc * 64 + cil;
        float w = K2[((size_t)co * 192 + ci) * 9 + tap];
        if (tap == 4 && ci == co) w -= 1.0f;
        g_w2[idx] = __float2bfloat16(w);
    }
}

__global__ void fin_kernel(float* __restrict__ out) {
    int t = threadIdx.x;
    out[X_ELEMS + t] = g_scalar + g_tld[t];
}

// ---------------- scalar logdet (verified) ----------------
__device__ __forceinline__ float2 cmul(float2 a, float2 b) {
    return make_float2(a.x * b.x - a.y * b.y, a.x * b.y + a.y * b.x);
}

__global__ void logdet_kernel(const float* __restrict__ K0, const float* __restrict__ a0,
                              const float* __restrict__ K1, const float* __restrict__ a1,
                              const float* __restrict__ K2, const float* __restrict__ a2) {
    const int L = blockIdx.x;
    const float* K = (L == 0) ? K0 : ((L == 1) ? K1 : K2);
    const float* als = (L == 0) ? a0 : ((L == 1) ? a1 : a2);
    const int c = (L == 0) ? 12 : ((L == 1) ? 48 : 192);
    const int n = (L == 0) ? 64 : ((L == 1) ? 32 : 16);

    __shared__ float sh_t[9];
    __shared__ float shS[81];
    __shared__ float red[16];
    const int tid = threadIdx.x;
    if (tid < 9) sh_t[tid] = 0.f;
    if (tid < 81) shS[tid] = 0.f;
    __syncthreads();

    float a81[81];
    float t9[9];
    #pragma unroll
    for (int k = 0; k < 81; k++) a81[k] = 0.f;
    #pragma unroll
    for (int k = 0; k < 9; k++) t9[k] = 0.f;

    for (int idx = tid; idx < c * c; idx += 256) {
        int i = idx / c, j = idx - i * c;
        const float* Ka = K + (size_t)(i * c + j) * 9;
        const float* Kb = K + (size_t)(j * c + i) * 9;
        float av[9], bv[9];
        #pragma unroll
        for (int a = 0; a < 9; a++) { av[a] = Ka[a]; bv[a] = Kb[a]; }
        #pragma unroll
        for (int a = 0; a < 9; a++)
            #pragma unroll
            for (int b = 0; b < 9; b++) a81[a * 9 + b] += av[a] * bv[b];
        if (i == j) {
            #pragma unroll
            for (int a = 0; a < 9; a++) t9[a] += av[a];
        }
    }
    #pragma unroll
    for (int k = 0; k < 81; k++) atomicAdd(&shS[k], a81[k]);
    #pragma unroll
    for (int k = 0; k < 9; k++) atomicAdd(&sh_t[k], t9[k]);
    __syncthreads();

    float part = 0.f;
    for (int f = tid; f < n * n; f += 256) {
        int u = f / n, v = f - u * n;
        float su, cu, sv, cv;
        sincosf(-6.283185307179586f * (float)u / (float)n, &su, &cu);
        sincosf(-6.283185307179586f * (float)v / (float)n, &sv, &cv);
        float2 eu = make_float2(cu, su), ev = make_float2(cv, sv);
        float2 pU[3] = {make_float2(1.f, 0.f), eu, cmul(eu, eu)};
        float2 pV[3] = {make_float2(1.f, 0.f), ev, cmul(ev, ev)};
        float2 ph[9];
        #pragma unroll
        for (int dy = 0; dy < 3; dy++)
            #pragma unroll
            for (int dx = 0; dx < 3; dx++) ph[dy * 3 + dx] = cmul(pU[dy], pV[dx]);

        float2 T = make_float2(0.f, 0.f), T2 = make_float2(0.f, 0.f);
        #pragma unroll
        for (int a = 0; a < 9; a++) {
            T.x += sh_t[a] * ph[a].x;
            T.y += sh_t[a] * ph[a].y;
        }
        #pragma unroll
        for (int a = 0; a < 9; a++) {
            float2 inner = make_float2(0.f, 0.f);
            #pragma unroll
            for (int b = 0; b < 9; b++) {
                float s = shS[a * 9 + b];
                inner.x += s * ph[b].x;
                inner.y += s * ph[b].y;
            }
            float2 pi = cmul(ph[a], inner);
            T2.x += pi.x;
            T2.y += pi.y;
        }
        float2 e1 = cmul(pU[1], pV[1]);
        e1.y = -e1.y;
        float2 e2 = cmul(e1, e1);
        float A = e1.x * T.x - e1.y * T.y;
        float B = e2.x * T2.x - e2.y * T2.y;
        part += 2.f * A - 1.5f * (float)c - 0.5f * B;
    }

    float as = 0.f;
    for (int k = tid; k < c; k += 256) as += als[k];

    float w1 = wred(part);
    float w2 = wred(as);
    int wid = tid >> 5;
    if ((tid & 31) == 0) { red[wid] = w1; red[wid + 8] = w2; }
    __syncthreads();
    if (tid == 0) {
        float s1 = 0.f, s2 = 0.f;
        #pragma unroll
        for (int w = 0; w < 8; w++) { s1 += red[w]; s2 += red[w + 8]; }
        atomicAdd(&g_scalar, s1 + (float)(n * n) * s2);
    }
}

// ---------------- layer 0: fused FFMA conv (verified R10) ----------------
__global__ void __launch_bounds__(256, 2)
conv_layer0(const float* __restrict__ X, const float* __restrict__ Kw,
            const float* __restrict__ cb, const float* __restrict__ ab,
            const float* __restrict__ als, float* __restrict__ Y,
            __nv_bfloat16* __restrict__ YB) {
    constexpr int CPREV = 3, N = 64, CI_CHUNK = 12, OUT_BLK = 12;
    constexpr int CIN = 12, H = 128;
    constexpr int S_FLOATS = CI_CHUNK * 324 * 4;
    extern __shared__ float smem[];
    float* S = smem;
    float2* KS = (float2*)(smem + S_FLOATS);
    float* sE = (float*)(KS + CI_CHUNK * 9 * OUT_BLK);
    float* sAb = sE + OUT_BLK;

    const int tid = threadIdx.x;
    const int bq = blockIdx.x;
    const int b0 = bq * 4;
    constexpr int TILES_X = N / 16;
    const int ty = (blockIdx.y / TILES_X) * 16;
    const int tx = (blockIdx.y % TILES_X) * 16;
    const int py = tid >> 4, px = tid & 15;

    if (tid < OUT_BLK) {
        sE[tid] = expf(als[tid]);
        sAb[tid] = ab[tid];
    }

    unsigned long long accA[OUT_BLK], accB[OUT_BLK];
    #pragma unroll
    for (int o = 0; o < OUT_BLK; o++) { accA[o] = 0ull; accB[o] = 0ull; }

    {
        __syncthreads();
        for (int idx = tid; idx < CI_CHUNK * 324; idx += 256) {
            int ci = idx / 324;
            int rem = idx - ci * 324;
            int yy = rem / 18, xx = rem - yy * 18;
            int g = ci / CPREV;
            int cc = ci - g * CPREV;
            int gy = ty + yy - 1;
            if (gy < 0) gy += N;
            if (gy >= N) gy -= N;
            int gx = tx + xx - 1;
            if (gx < 0) gx += N;
            if (gx >= N) gx -= N;
            int sy = 2 * gy + (g & 1);
            int sx = 2 * gx + ((g ^ (g >> 1)) & 1);
            size_t base = ((size_t)cc * H + sy) * H + sx;
            size_t bstr = (size_t)CPREV * H * H;
            float4 val;
            val.x = X[base + (size_t)(b0 + 0) * bstr];
            val.y = X[base + (size_t)(b0 + 1) * bstr];
            val.z = X[base + (size_t)(b0 + 2) * bstr];
            val.w = X[base + (size_t)(b0 + 3) * bstr];
            *(float4*)(S + idx * 4) = val;
        }
        for (int idx = tid; idx < CI_CHUNK * 9 * OUT_BLK; idx += 256) {
            int ci = idx / (9 * OUT_BLK);
            int rem = idx - ci * 9 * OUT_BLK;
            int tap = rem / OUT_BLK;
            int o = rem - tap * OUT_BLK;
            float k = Kw[((size_t)o * CIN + ci) * 9 + tap];
            KS[idx] = make_float2(k, k);
        }
        __syncthreads();

        #pragma unroll 1
        for (int ci = 0; ci < CI_CHUNK; ci++) {
            const float* Sci = S + ci * 1296;
            const float2* Kci = KS + ci * 9 * OUT_BLK;
            #pragma unroll
            for (int tap = 0; tap < 9; tap++) {
                int dy = tap / 3, dx = tap - dy * 3;
                ulonglong2 v =
                    *(const ulonglong2*)(Sci + ((py + dy) * 18 + (px + dx)) * 4);
                #pragma unroll
                for (int o = 0; o < OUT_BLK; o += 2) {
                    ulonglong2 kk = *(const ulonglong2*)(Kci + tap * OUT_BLK + o);
                    ffma2(accA[o], kk.x, v.x);
                    ffma2(accB[o], kk.x, v.y);
                    ffma2(accA[o + 1], kk.y, v.x);
                    ffma2(accB[o + 1], kk.y, v.y);
                }
            }
        }
    }

    const int i = ty + py, j = tx + px;
    float ld[4] = {0.f, 0.f, 0.f, 0.f};
    uint32_t pk[6][4];

    #pragma unroll
    for (int o = 0; o < OUT_BLK; o += 2) {
        float e0 = sE[o], a0v = sAb[o];
        float e1 = sE[o + 1], a1v = sAb[o + 1];
        float c0v = cb[((size_t)o * N + i) * N + j];
        float c1v = cb[((size_t)(o + 1) * N + i) * N + j];
        float2 pA0 = up2(accA[o]), pB0 = up2(accB[o]);
        float2 pA1 = up2(accA[o + 1]), pB1 = up2(accB[o + 1]);
        float z0[4] = {pA0.x, pA0.y, pB0.x, pB0.y};
        float z1[4] = {pA1.x, pA1.y, pB1.x, pB1.y};
        float t0[4], t1[4];
        #pragma unroll
        for (int nb = 0; nb < 4; nb++) {
            t0[nb] = tanhf((z0[nb] + c0v) * e0 + a0v);
            t1[nb] = tanhf((z1[nb] + c1v) * e1 + a1v);
            ld[nb] += log1pf(-t0[nb] * t0[nb]) + log1pf(-t1[nb] * t1[nb]);
            __nv_bfloat162 p2;
            p2.x = __float2bfloat16(t0[nb]);
            p2.y = __float2bfloat16(t1[nb]);
            pk[o >> 1][nb] = *(uint32_t*)&p2;
        }
        *(float4*)(Y + ((((size_t)bq * 12 + o) * N + i) * N + j) * 4) =
            make_float4(t0[0], t0[1], t0[2], t0[3]);
        *(float4*)(Y + ((((size_t)bq * 12 + o + 1) * N + i) * N + j) * 4) =
            make_float4(t1[0], t1[1], t1[2], t1[3]);
    }

    {
        const int y = i >> 1, x = j >> 1;
        const int hs = i & 1, ws = j & 1;
        const int g = (hs == ws) ? hs : (2 + hs);
        #pragma unroll
        for (int nb = 0; nb < 4; nb++) {
            size_t base = ((size_t)(b0 + nb) * 1024 + y * 32 + x) * 64 + g * 12;
            *(uint2*)(YB + base) = make_uint2(pk[0][nb], pk[1][nb]);
            *(uint2*)(YB + base + 4) = make_uint2(pk[2][nb], pk[3][nb]);
            *(uint2*)(YB + base + 8) = make_uint2(pk[4][nb], pk[5][nb]);
        }
    }

    #pragma unroll
    for (int nb = 0; nb < 4; nb++) ld[nb] = wred(ld[nb]);
    __syncthreads();
    float* red = S;
    if ((tid & 31) == 0) {
        int w = tid >> 5;
        red[w * 4 + 0] = ld[0];
        red[w * 4 + 1] = ld[1];
        red[w * 4 + 2] = ld[2];
        red[w * 4 + 3] = ld[3];
    }
    __syncthreads();
    if (tid < 4) {
        float s = 0.f;
        #pragma unroll
        for (int w = 0; w < 8; w++) s += red[w * 4 + tid];
        atomicAdd(&g_tld[b0 + tid], s);
    }
}

// ---------------- layer 1: HMMA, single-stage smem (act halo + ALL weights) ---
// smem: act halo 320 rows x 128B @0 (40KB), weights 9x64 rows x 128B @40960 (72KB)
// Tap shift applied at ldmatrix address time (row permutation) -> zero re-staging.
#define L1_WT_BASE 40960
#define L1_SMEM 114688

__global__ void __launch_bounds__(256, 2)
l1_mma(const __nv_bfloat16* __restrict__ ag, const float* __restrict__ x1p,
       const float* __restrict__ cb, const float* __restrict__ ab,
       const float* __restrict__ als,
       __nv_bfloat16* __restrict__ xg, float* __restrict__ xf) {
    extern __shared__ char smc[];
    uint32_t smem_base = smem_u32(smc);
    const int tid = threadIdx.x;
    const int lane = tid & 31, wid = tid >> 5;
    const int b = blockIdx.x;
    const int mt0 = blockIdx.y * 256;
    const int ytile0 = mt0 >> 5;        // 0,8,16,24
    const int m0 = (wid & 3) * 64;
    const int n0 = (wid >> 2) * 32;
    const int bq = b >> 2, nb = b & 3;

    // stage act halo: 320 rows (y = ytile0-1 .. ytile0+8 wrapped, 32 x each)
    for (int r = tid; r < 320; r += 256) {
        int yrel = r >> 5, x = r & 31;
        int yg = (ytile0 - 1 + yrel) & 31;
        const char* src = (const char*)(ag + ((size_t)b * 1024 + yg * 32 + x) * 64);
        #pragma unroll
        for (int s = 0; s < 8; s++) {
            uint32_t off = (uint32_t)r * 128 + s * 16;
            cpasync16(smem_base + swz(off), src + s * 16);
        }
    }
    // stage ALL weights: 576 rows
    for (int r = tid; r < 576; r += 256) {
        const char* src = (const char*)(g_w1 + (size_t)r * 64);
        #pragma unroll
        for (int s = 0; s < 8; s++) {
            uint32_t off = (uint32_t)r * 128 + s * 16;
            cpasync16(smem_base + L1_WT_BASE + swz(off), src + s * 16);
        }
    }
    cpasync_commit();

    float d[4][4][4];
    #pragma unroll
    for (int mt = 0; mt < 4; mt++)
        #pragma unroll
        for (int nt = 0; nt < 4; nt++)
            #pragma unroll
            for (int r = 0; r < 4; r++) d[mt][nt][r] = 0.f;

    // per-(mt) base pixel coords for this lane
    int ply[4], plx[4];
    #pragma unroll
    for (int mt = 0; mt < 4; mt++) {
        int pl = m0 + mt * 16 + (lane & 15);
        ply[mt] = pl >> 5;
        plx[mt] = pl & 31;
    }

    cpasync_wait<0>();
    __syncthreads();

    #pragma unroll 1
    for (int c = 0; c < 9; c++) {
        int dy = c / 3 - 1, dx = c % 3 - 1;
        #pragma unroll
        for (int ks = 0; ks < 4; ks++) {
            uint32_t a[4][4];
            #pragma unroll
            for (int mt = 0; mt < 4; mt++) {
                int row = (ply[mt] + 1 + dy) * 32 + ((plx[mt] + dx) & 31);
                uint32_t off = (uint32_t)row * 128 + ks * 32 + (lane >> 4) * 16;
                ldsm4(a[mt], smem_base + swz(off));
            }
            uint32_t bf[2][4];
            #pragma unroll
            for (int nh = 0; nh < 2; nh++) {
                uint32_t row = c * 64 + n0 + nh * 16 + (lane & 7) + ((lane >> 4) << 3);
                uint32_t off = row * 128 + ks * 32 + ((lane >> 3) & 1) * 16;
                ldsm4(bf[nh], smem_base + L1_WT_BASE + swz(off));
            }
            #pragma unroll
            for (int mt = 0; mt < 4; mt++)
                #pragma unroll
                for (int nt = 0; nt < 4; nt++)
                    mma16816(d[mt][nt], a[mt], &bf[nt >> 1][(nt & 1) * 2]);
        }
    }

    // epilogue: center add (from packed fp32 x1) + cb + actnorm + tanh + logdet
    float ldsum = 0.f;
    #pragma unroll
    for (int nt = 0; nt < 4; nt++) {
        int co = n0 + nt * 8 + (lane & 3) * 2;
        if (co < 48) {
            int g0 = co / 12, c0 = co - g0 * 12;
            int co1 = co + 1;
            int g1 = co1 / 12, c1 = co1 - g1 * 12;
            int hs0 = g0 & 1, ws0 = (g0 ^ (g0 >> 1)) & 1;
            int hs1 = g1 & 1, ws1 = (g1 ^ (g1 >> 1)) & 1;
            float e0 = expf(als[co]), e1 = expf(als[co1]);
            float ab0 = ab[co], ab1 = ab[co1];
            #pragma unroll
            for (int mt = 0; mt < 4; mt++) {
                #pragma unroll
                for (int half = 0; half < 2; half++) {
                    int p = mt0 + m0 + mt * 16 + (lane >> 2) + half * 8;
                    int i = p >> 5, j = p & 31;
                    float xc0 = x1p[((((size_t)bq * 12 + c0) * 64 + (2 * i + hs0)) * 64 +
                                     (2 * j + ws0)) * 4 + nb];
                    float xc1 = x1p[((((size_t)bq * 12 + c1) * 64 + (2 * i + hs1)) * 64 +
                                     (2 * j + ws1)) * 4 + nb];
                    float z0 = d[mt][nt][half * 2] + xc0 + cb[(size_t)co * 1024 + p];
                    float z1 = d[mt][nt][half * 2 + 1] + xc1 + cb[(size_t)co1 * 1024 + p];
                    float t0 = tanhf(z0 * e0 + ab0);
                    float t1 = tanhf(z1 * e1 + ab1);
                    ldsum += log1pf(-t0 * t0) + log1pf(-t1 * t1);
                    int y = i >> 1, x = j >> 1;
                    int hs = i & 1, ws = j & 1;
                    int g = (hs == ws) ? hs : (2 + hs);
                    size_t xi = ((size_t)b * 256 + y * 16 + x) * 192 + g * 48 + co;
                    __nv_bfloat162 pk2;
                    pk2.x = __float2bfloat16(t0);
                    pk2.y = __float2bfloat16(t1);
                    *(__nv_bfloat162*)(xg + xi) = pk2;
                    *(float2*)(xf + xi) = make_float2(t0, t1);
                }
            }
        }
    }
    ldsum = wred(ldsum);
    __shared__ float red[8];
    if (lane == 0) red[wid] = ldsum;
    __syncthreads();
    if (tid == 0) {
        float s = 0.f;
        #pragma unroll
        for (int w = 0; w < 8; w++) s += red[w];
        atomicAdd(&g_tld[b], s);
    }
}

// ---------------- layer 2: HMMA, act slabs staged once + dbuf weights ---------
// smem: 3 act slabs (cc) x 256 rows x 128B @0/32768/65536, wt dbuf @98304+buf*8192
#define L2_WT_BASE 98304
#define L2_SMEM 114688

__device__ __forceinline__ void l2_stage_wt(uint32_t smem_base, int buf, int c,
                                            int co0, int tid) {
    if (tid < 64) {
        const char* src = (const char*)(g_w2 + ((size_t)c * 192 + co0 + tid) * 64);
        uint32_t ra = smem_base + L2_WT_BASE + buf * 8192;
        #pragma unroll
        for (int s = 0; s < 8; s++) {
            uint32_t off = (uint32_t)tid * 128 + s * 16;
            cpasync16(ra + swz(off), src + s * 16);
        }
    }
    cpasync_commit();
}

__global__ void __launch_bounds__(256, 2)
l2_mma(const __nv_bfloat16* __restrict__ xg, const float* __restrict__ xf,
       const float* __restrict__ cb, const float* __restrict__ ab,
       const float* __restrict__ als, float* __restrict__ out) {
    extern __shared__ char smc[];
    uint32_t smem_base = smem_u32(smc);
    const int tid = threadIdx.x;
    const int lane = tid & 31, wid = tid >> 5;
    const int b = blockIdx.x;
    const int co0 = blockIdx.y * 64;
    const int m0 = (wid & 3) * 64;
    const int n0 = (wid >> 2) * 32;

    // stage ALL 3 act slabs (768 rows) + first weight chunk, one group
    for (int r = tid; r < 768; r += 256) {
        int cc = r >> 8, p = r & 255;
        const char* src = (const char*)(xg + ((size_t)b * 256 + p) * 192 + cc * 64);
        uint32_t base = smem_base + cc * 32768;
        #pragma unroll
        for (int s = 0; s < 8; s++) {
            uint32_t off = (uint32_t)p * 128 + s * 16;
            cpasync16(base + swz(off), src + s * 16);
        }
    }
    l2_stage_wt(smem_base, 0, 0, co0, tid);  // commits the group

    float d[4][4][4];
    #pragma unroll
    for (int mt = 0; mt < 4; mt++)
        #pragma unroll
        for (int nt = 0; nt < 4; nt++)
            #pragma unroll
            for (int r = 0; r < 4; r++) d[mt][nt][r] = 0.f;

    int ply[4], plx[4];
    #pragma unroll
    for (int mt = 0; mt < 4; mt++) {
        int pl = m0 + mt * 16 + (lane & 15);
        ply[mt] = pl >> 4;
        plx[mt] = pl & 15;
    }

    #pragma unroll 1
    for (int c = 0; c < 27; c++) {
        int cur = c & 1;
        if (c + 1 < 27) {
            l2_stage_wt(smem_base, 1 - cur, c + 1, co0, tid);
            cpasync_wait<1>();
        } else {
            cpasync_wait<0>();
        }
        __syncthreads();
        int tap = c / 3, cc = c - tap * 3;
        int dy = tap / 3 - 1, dx = tap % 3 - 1;
        uint32_t actb = smem_base + cc * 32768;
        uint32_t wtb = smem_base + L2_WT_BASE + cur * 8192;
        #pragma unroll
        for (int ks = 0; ks < 4; ks++) {
            uint32_t a[4][4];
            #pragma unroll
            for (int mt = 0; mt < 4; mt++) {
                int row = ((ply[mt] + dy) & 15) * 16 + ((plx[mt] + dx) & 15);
                uint32_t off = (uint32_t)row * 128 + ks * 32 + (lane >> 4) * 16;
                ldsm4(a[mt], actb + swz(off));
            }
            uint32_t bf[2][4];
            #pragma unroll
            for (int nh = 0; nh < 2; nh++) {
                uint32_t row = n0 + nh * 16 + (lane & 7) + ((lane >> 4) << 3);
                uint32_t off = row * 128 + ks * 32 + ((lane >> 3) & 1) * 16;
                ldsm4(bf[nh], wtb + swz(off));
            }
            #pragma unroll
            for (int mt = 0; mt < 4; mt++)
                #pragma unroll
                for (int nt = 0; nt < 4; nt++)
                    mma16816(d[mt][nt], a[mt], &bf[nt >> 1][(nt & 1) * 2]);
        }
        __syncthreads();
    }

    #pragma unroll
    for (int nt = 0; nt < 4; nt++) {
        int co = co0 + n0 + nt * 8 + (lane & 3) * 2;
        float e0 = expf(als[co]), e1 = expf(als[co + 1]);
        float ab0 = ab[co], ab1 = ab[co + 1];
        const float* cb0p = cb + (size_t)co * 256;
        const float* cb1p = cb + (size_t)(co + 1) * 256;
        float* o0p = out + ((size_t)b * 192 + co) * 256;
        float* o1p = out + ((size_t)b * 192 + co + 1) * 256;
        #pragma unroll
        for (int mt = 0; mt < 4; mt++) {
            int p = m0 + mt * 16 + (lane >> 2);
            const float* xf0 = xf + ((size_t)b * 256 + p) * 192;
            const float* xf8 = xf + ((size_t)b * 256 + p + 8) * 192;
            o0p[p] = (d[mt][nt][0] + xf0[co] + cb0p[p]) * e0 + ab0;
            o1p[p] = (d[mt][nt][1] + xf0[co + 1] + cb1p[p]) * e1 + ab1;
            o0p[p + 8] = (d[mt][nt][2] + xf8[co] + cb0p[p + 8]) * e0 + ab0;
            o1p[p + 8] = (d[mt][nt][3] + xf8[co + 1] + cb1p[p + 8]) * e1 + ab1;
        }
    }
}

// ---------------- launch ----------------
extern "C" void kernel_launch(void* const* d_in, const int* in_sizes, int n_in,
                              void* d_out, int out_size) {
    const float* x = (const float*)d_in[0];
    const float* k0 = (const float*)d_in[1];
    const float* cb0 = (const float*)d_in[2];
    const float* ab0 = (const float*)d_in[3];
    const float* als0 = (const float*)d_in[4];
    const float* k1 = (const float*)d_in[5];
    const float* cb1 = (const float*)d_in[6];
    const float* ab1 = (const float*)d_in[7];
    const float* als1 = (const float*)d_in[8];
    const float* k2 = (const float*)d_in[9];
    const float* cb2 = (const float*)d_in[10];
    const float* ab2 = (const float*)d_in[11];
    const float* als2 = (const float*)d_in[12];
    float* out = (float*)d_out;

    float *x1, *xf;
    __nv_bfloat16 *ag1, *xg;
    cudaGetSymbolAddress((void**)&x1, g_x1);
    cudaGetSymbolAddress((void**)&ag1, g_ag1);
    cudaGetSymbolAddress((void**)&xg, g_xg);
    cudaGetSymbolAddress((void**)&xf, g_xf32);

    const int SM0 = 12 * 324 * 4 * 4 + 12 * 9 * 12 * 8 + 12 * 2 * 4;
    cudaFuncSetAttribute((const void*)conv_layer0,
                         cudaFuncAttributeMaxDynamicSharedMemorySize, SM0);
    cudaFuncSetAttribute((const void*)l1_mma,
                         cudaFuncAttributeMaxDynamicSharedMemorySize, L1_SMEM);
    cudaFuncSetAttribute((const void*)l2_mma,
                         cudaFuncAttributeMaxDynamicSharedMemorySize, L2_SMEM);

    // launch 1: fused setup (init + ag1 pad + w1 + w2 prep)
    setup_kernel<<<2465, 256>>>(k1, k2);
    // launch 2: scalar logdets
    logdet_kernel<<<3, 256>>>(k0, als0, k1, als1, k2, als2);
    // launch 3: layer 0 FFMA conv
    conv_layer0<<<dim3(64, 16, 1), 256, SM0>>>(x, k0, cb0, ab0, als0, x1, ag1);
    // launch 4 (profiled slot): layer 1 HMMA
    l1_mma<<<dim3(256, 4), 256, L1_SMEM>>>(ag1, x1, cb1, ab1, als1, xg, xf);
    // launch 5: layer 2 HMMA
    l2_mma<<<dim3(256, 3), 256, L2_SMEM>>>(xg, xf, cb2, ab2, als2, out);
    // launch 6: finalize logdet outputs
    fin_kernel<<<1, 256>>>(out);
}

// round 12
// speedup vs baseline: 2.3401x; 1.1649x over previous
#include <cuda_runtime.h>
#include <cuda_bf16.h>
#include <cstdint>

// ---------------- device scratch (no allocations allowed) ----------------
__device__ __align__(16) float g_x1[256 * 12 * 64 * 64];          // L0 out squeezed-co fp32 [bq][48][1024][4]
__device__ __align__(16) __nv_bfloat16 g_ag1[256 * 1024 * 64];    // L0 out squeezed bf16 [b][p][ci(48,pad64)]
__device__ __align__(16) __nv_bfloat16 g_w1[9 * 64 * 64];         // L1 residual weights (K1 - I) bf16, padded
__device__ __align__(16) __nv_bfloat16 g_xg[256 * 256 * 192];     // L2 input bf16 [b][p][ci]
__device__ __align__(16) float g_xf32[256 * 256 * 192];           // same, fp32 (L2 center add)
__device__ __align__(16) __nv_bfloat16 g_w2[9 * 3 * 192 * 64];    // L2 residual weights (K2 - I) bf16
__device__ float g_tld[256];
__device__ float g_trT[3][9];     // kernel tap traces (L0, L1 direct)
__device__ float g_trS[3][81];    // tap-pair traces
__device__ float g_t2p[16][9];    // L2 partials
__device__ float g_s2p[16][81];

#define X_ELEMS (256 * 192 * 16 * 16)

// ---------------- packed f32x2 helpers ----------------
__device__ __forceinline__ void ffma2(unsigned long long& d, unsigned long long a,
                                      unsigned long long b) {
    asm("fma.rn.f32x2 %0, %1, %2, %0;" : "+l"(d) : "l"(a), "l"(b));
}
__device__ __forceinline__ float2 up2(unsigned long long v) {
    float2 f;
    asm("mov.b64 {%0,%1}, %2;" : "=f"(f.x), "=f"(f.y) : "l"(v));
    return f;
}
__device__ __forceinline__ float wred(float v) {
    #pragma unroll
    for (int o = 16; o; o >>= 1) v += __shfl_xor_sync(0xffffffffu, v, o);
    return v;
}

// ---------------- PTX helpers ----------------
__device__ __forceinline__ uint32_t smem_u32(const void* p) {
    uint32_t a;
    asm("{ .reg .u64 t; cvta.to.shared.u64 t, %1; cvt.u32.u64 %0, t; }" : "=r"(a) : "l"(p));
    return a;
}
__device__ __forceinline__ void cpasync16(uint32_t dst, const void* src) {
    asm volatile("cp.async.cg.shared.global [%0], [%1], 16;" :: "r"(dst), "l"(src));
}
__device__ __forceinline__ void cpasync_commit() {
    asm volatile("cp.async.commit_group;" ::: "memory");
}
template <int N>
__device__ __forceinline__ void cpasync_wait() {
    asm volatile("cp.async.wait_group %0;" :: "n"(N) : "memory");
}
__device__ __forceinline__ void ldsm4(uint32_t* r, uint32_t addr) {
    asm volatile("ldmatrix.sync.aligned.m8n8.x4.shared.b16 {%0,%1,%2,%3}, [%4];"
                 : "=r"(r[0]), "=r"(r[1]), "=r"(r[2]), "=r"(r[3]) : "r"(addr));
}
__device__ __forceinline__ void mma16816(float* d, const uint32_t* a, const uint32_t* b) {
    asm volatile(
        "mma.sync.aligned.m16n8k16.row.col.f32.bf16.bf16.f32 "
        "{%0,%1,%2,%3}, {%4,%5,%6,%7}, {%8,%9}, {%0,%1,%2,%3};"
        : "+f"(d[0]), "+f"(d[1]), "+f"(d[2]), "+f"(d[3])
        : "r"(a[0]), "r"(a[1]), "r"(a[2]), "r"(a[3]), "r"(b[0]), "r"(b[1]));
}
__device__ __forceinline__ uint32_t swz(uint32_t off) { return off ^ ((off >> 3) & 0x70); }

// ---------------- trace accumulation (partial pair range) ----------------
__device__ void trace_accum(const float* __restrict__ K, int c, int lo, int hi,
                            float* __restrict__ gT, float* __restrict__ gS) {
    __shared__ float shS[81];
    __shared__ float shT[9];
    const int tid = threadIdx.x;
    if (tid < 81) shS[tid] = 0.f;
    if (tid < 9) shT[tid] = 0.f;
    __syncthreads();
    float a81[81], t9[9];
    #pragma unroll
    for (int k = 0; k < 81; k++) a81[k] = 0.f;
    #pragma unroll
    for (int k = 0; k < 9; k++) t9[k] = 0.f;
    for (int idx = lo + tid; idx < hi; idx += 256) {
        int i = idx / c, j = idx - i * c;
        const float* Ka = K + (size_t)(i * c + j) * 9;
        const float* Kb = K + (size_t)(j * c + i) * 9;
        float av[9], bv[9];
        #pragma unroll
        for (int a = 0; a < 9; a++) { av[a] = Ka[a]; bv[a] = Kb[a]; }
        #pragma unroll
        for (int a = 0; a < 9; a++)
            #pragma unroll
            for (int b = 0; b < 9; b++) a81[a * 9 + b] += av[a] * bv[b];
        if (i == j) {
            #pragma unroll
            for (int a = 0; a < 9; a++) t9[a] += av[a];
        }
    }
    #pragma unroll
    for (int k = 0; k < 81; k++) atomicAdd(&shS[k], a81[k]);
    #pragma unroll
    for (int k = 0; k < 9; k++) atomicAdd(&shT[k], t9[k]);
    __syncthreads();
    if (tid < 81) gS[tid] = shS[tid];
    if (tid < 9) gT[tid] = shT[tid];
}

// ---------------- fused setup: tld init + ag1 pad + w1/w2 prep + traces ------
// blocks: [0] tld, [1..1024] ag1 pad, [1025..1168] w1, [1169..2464] w2,
//         [2465] trace L0, [2466] trace L1, [2467..2482] trace L2 partials
__global__ void setup_kernel(const float* __restrict__ K0, const float* __restrict__ K1,
                             const float* __restrict__ K2) {
    int bid = blockIdx.x, tid = threadIdx.x;
    if (bid == 0) {
        g_tld[tid] = 0.f;
    } else if (bid <= 1024) {
        int idx = (bid - 1) * 256 + tid;
        uint4 z = make_uint4(0, 0, 0, 0);
        *(uint4*)(g_ag1 + (size_t)idx * 64 + 48) = z;
        *(uint4*)(g_ag1 + (size_t)idx * 64 + 56) = z;
    } else if (bid <= 1168) {
        int idx = (bid - 1025) * 256 + tid;
        int cil = idx & 63;
        int r = idx >> 6;
        int co = r % 64;
        int tap = r / 64;
        float w = 0.f;
        if (co < 48 && cil < 48) {
            w = K1[((size_t)co * 48 + cil) * 9 + tap];
            if (tap == 4 && cil == co) w -= 1.0f;
        }
        g_w1[idx] = __float2bfloat16(w);
    } else if (bid <= 2464) {
        int idx = (bid - 1169) * 256 + tid;
        int cil = idx & 63;
        int r = idx >> 6;
        int co = r % 192;
        int q = r / 192;
        int cc = q % 3;
        int tap = q / 3;
        int ci = cc * 64 + cil;
        float w = K2[((size_t)co * 192 + ci) * 9 + tap];
        if (tap == 4 && ci == co) w -= 1.0f;
        g_w2[idx] = __float2bfloat16(w);
    } else if (bid == 2465) {
        trace_accum(K0, 12, 0, 144, g_trT[0], g_trS[0]);
    } else if (bid == 2466) {
        trace_accum(K1, 48, 0, 2304, g_trT[1], g_trS[1]);
    } else {
        int blk = bid - 2467;
        trace_accum(K2, 192, blk * 2304, (blk + 1) * 2304, g_t2p[blk], g_s2p[blk]);
    }
}

// ---------------- finalize: frequency sums + als sums + tanh logdet ----------
__device__ __forceinline__ float2 cmul(float2 a, float2 b) {
    return make_float2(a.x * b.x - a.y * b.y, a.x * b.y + a.y * b.x);
}

__global__ void fin_kernel(const float* __restrict__ a0, const float* __restrict__ a1,
                           const float* __restrict__ a2, float* __restrict__ out) {
    __shared__ float shT[9], shS[81], red[8];
    __shared__ float stot;
    const int tid = threadIdx.x;
    float part = 0.f;
    #pragma unroll 1
    for (int L = 0; L < 3; L++) {
        const float* als = (L == 0) ? a0 : ((L == 1) ? a1 : a2);
        const int c = (L == 0) ? 12 : ((L == 1) ? 48 : 192);
        const int n = (L == 0) ? 64 : ((L == 1) ? 32 : 16);
        __syncthreads();
        if (tid < 9) {
            float s;
            if (L < 2) s = g_trT[L][tid];
            else {
                s = 0.f;
                #pragma unroll
                for (int p = 0; p < 16; p++) s += g_t2p[p][tid];
            }
            shT[tid] = s;
        }
        if (tid < 81) {
            float s;
            if (L < 2) s = g_trS[L][tid];
            else {
                s = 0.f;
                #pragma unroll
                for (int p = 0; p < 16; p++) s += g_s2p[p][tid];
            }
            shS[tid] = s;
        }
        __syncthreads();
        for (int f = tid; f < n * n; f += 256) {
            int u = f / n, v = f - u * n;
            float su, cu, sv, cv;
            sincosf(-6.283185307179586f * (float)u / (float)n, &su, &cu);
            sincosf(-6.283185307179586f * (float)v / (float)n, &sv, &cv);
            float2 eu = make_float2(cu, su), ev = make_float2(cv, sv);
            float2 pU[3] = {make_float2(1.f, 0.f), eu, cmul(eu, eu)};
            float2 pV[3] = {make_float2(1.f, 0.f), ev, cmul(ev, ev)};
            float2 ph[9];
            #pragma unroll
            for (int dy = 0; dy < 3; dy++)
                #pragma unroll
                for (int dx = 0; dx < 3; dx++) ph[dy * 3 + dx] = cmul(pU[dy], pV[dx]);
            float2 T = make_float2(0.f, 0.f), T2 = make_float2(0.f, 0.f);
            #pragma unroll
            for (int a = 0; a < 9; a++) {
                T.x += shT[a] * ph[a].x;
                T.y += shT[a] * ph[a].y;
            }
            #pragma unroll
            for (int a = 0; a < 9; a++) {
                float2 inner = make_float2(0.f, 0.f);
                #pragma unroll
                for (int b = 0; b < 9; b++) {
                    float s = shS[a * 9 + b];
                    inner.x += s * ph[b].x;
                    inner.y += s * ph[b].y;
                }
                float2 pi = cmul(ph[a], inner);
                T2.x += pi.x;
                T2.y += pi.y;
            }
            float2 e1 = cmul(pU[1], pV[1]);
            e1.y = -e1.y;
            float2 e2 = cmul(e1, e1);
            float A = e1.x * T.x - e1.y * T.y;
            float B = e2.x * T2.x - e2.y * T2.y;
            part += 2.f * A - 1.5f * (float)c - 0.5f * B;
        }
        float as = 0.f;
        for (int k = tid; k < c; k += 256) as += als[k];
        part += (float)(n * n) * as;
    }
    float w = wred(part);
    if ((tid & 31) == 0) red[tid >> 5] = w;
    __syncthreads();
    if (tid == 0) {
        float s = 0.f;
        #pragma unroll
        for (int q = 0; q < 8; q++) s += red[q];
        stot = s;
    }
    __syncthreads();
    out[X_ELEMS + tid] = stot + g_tld[tid];
}

// ---------------- layer 0: fused FFMA conv ----------------
// Outputs: x1sq fp32 [bq][co=g*12+o][p=1024][4] (squeezed-co, for L1 center add)
//          ag1 bf16 [b][p][ci pad 64] (batched 8B stores, for L1 MMA)
__global__ void __launch_bounds__(256, 2)
conv_layer0(const float* __restrict__ X, const float* __restrict__ Kw,
            const float* __restrict__ cb, const float* __restrict__ ab,
            const float* __restrict__ als, float* __restrict__ Y,
            __nv_bfloat16* __restrict__ YB) {
    constexpr int CPREV = 3, N = 64, CI_CHUNK = 12, OUT_BLK = 12;
    constexpr int CIN = 12, H = 128;
    constexpr int S_FLOATS = CI_CHUNK * 324 * 4;
    extern __shared__ float smem[];
    float* S = smem;
    float2* KS = (float2*)(smem + S_FLOATS);
    float* sE = (float*)(KS + CI_CHUNK * 9 * OUT_BLK);
    float* sAb = sE + OUT_BLK;

    const int tid = threadIdx.x;
    const int bq = blockIdx.x;
    const int b0 = bq * 4;
    constexpr int TILES_X = N / 16;
    const int ty = (blockIdx.y / TILES_X) * 16;
    const int tx = (blockIdx.y % TILES_X) * 16;
    const int py = tid >> 4, px = tid & 15;

    if (tid < OUT_BLK) {
        sE[tid] = expf(als[tid]);
        sAb[tid] = ab[tid];
    }

    unsigned long long accA[OUT_BLK], accB[OUT_BLK];
    #pragma unroll
    for (int o = 0; o < OUT_BLK; o++) { accA[o] = 0ull; accB[o] = 0ull; }

    {
        __syncthreads();
        for (int idx = tid; idx < CI_CHUNK * 324; idx += 256) {
            int ci = idx / 324;
            int rem = idx - ci * 324;
            int yy = rem / 18, xx = rem - yy * 18;
            int g = ci / CPREV;
            int cc = ci - g * CPREV;
            int gy = ty + yy - 1;
            if (gy < 0) gy += N;
            if (gy >= N) gy -= N;
            int gx = tx + xx - 1;
            if (gx < 0) gx += N;
            if (gx >= N) gx -= N;
            int sy = 2 * gy + (g & 1);
            int sx = 2 * gx + ((g ^ (g >> 1)) & 1);
            size_t base = ((size_t)cc * H + sy) * H + sx;
            size_t bstr = (size_t)CPREV * H * H;
            float4 val;
            val.x = X[base + (size_t)(b0 + 0) * bstr];
            val.y = X[base + (size_t)(b0 + 1) * bstr];
            val.z = X[base + (size_t)(b0 + 2) * bstr];
            val.w = X[base + (size_t)(b0 + 3) * bstr];
            *(float4*)(S + idx * 4) = val;
        }
        for (int idx = tid; idx < CI_CHUNK * 9 * OUT_BLK; idx += 256) {
            int ci = idx / (9 * OUT_BLK);
            int rem = idx - ci * 9 * OUT_BLK;
            int tap = rem / OUT_BLK;
            int o = rem - tap * OUT_BLK;
            float k = Kw[((size_t)o * CIN + ci) * 9 + tap];
            KS[idx] = make_float2(k, k);
        }
        __syncthreads();

        #pragma unroll 1
        for (int ci = 0; ci < CI_CHUNK; ci++) {
            const float* Sci = S + ci * 1296;
            const float2* Kci = KS + ci * 9 * OUT_BLK;
            #pragma unroll
            for (int tap = 0; tap < 9; tap++) {
                int dy = tap / 3, dx = tap - dy * 3;
                ulonglong2 v =
                    *(const ulonglong2*)(Sci + ((py + dy) * 18 + (px + dx)) * 4);
                #pragma unroll
                for (int o = 0; o < OUT_BLK; o += 2) {
                    ulonglong2 kk = *(const ulonglong2*)(Kci + tap * OUT_BLK + o);
                    ffma2(accA[o], kk.x, v.x);
                    ffma2(accB[o], kk.x, v.y);
                    ffma2(accA[o + 1], kk.y, v.x);
                    ffma2(accB[o + 1], kk.y, v.y);
                }
            }
        }
    }

    const int i = ty + py, j = tx + px;
    const int y = i >> 1, x = j >> 1;
    const int hs = i & 1, ws = j & 1;
    const int g = (hs == ws) ? hs : (2 + hs);
    const int p = y * 32 + x;
    float ld[4] = {0.f, 0.f, 0.f, 0.f};
    uint32_t pk[6][4];

    #pragma unroll
    for (int o = 0; o < OUT_BLK; o += 2) {
        float e0 = sE[o], a0v = sAb[o];
        float e1 = sE[o + 1], a1v = sAb[o + 1];
        float c0v = cb[((size_t)o * N + i) * N + j];
        float c1v = cb[((size_t)(o + 1) * N + i) * N + j];
        float2 pA0 = up2(accA[o]), pB0 = up2(accB[o]);
        float2 pA1 = up2(accA[o + 1]), pB1 = up2(accB[o + 1]);
        float z0[4] = {pA0.x, pA0.y, pB0.x, pB0.y};
        float z1[4] = {pA1.x, pA1.y, pB1.x, pB1.y};
        float t0[4], t1[4];
        #pragma unroll
        for (int nb = 0; nb < 4; nb++) {
            t0[nb] = tanhf((z0[nb] + c0v) * e0 + a0v);
            t1[nb] = tanhf((z1[nb] + c1v) * e1 + a1v);
            ld[nb] += log1pf(-t0[nb] * t0[nb]) + log1pf(-t1[nb] * t1[nb]);
            __nv_bfloat162 p2;
            p2.x = __float2bfloat16(t0[nb]);
            p2.y = __float2bfloat16(t1[nb]);
            pk[o >> 1][nb] = *(uint32_t*)&p2;
        }
        // squeezed-co fp32 stores: x1sq[bq][g*12+o][p][nb]
        *(float4*)(Y + (((size_t)bq * 48 + g * 12 + o) * 1024 + p) * 4) =
            make_float4(t0[0], t0[1], t0[2], t0[3]);
        *(float4*)(Y + (((size_t)bq * 48 + g * 12 + o + 1) * 1024 + p) * 4) =
            make_float4(t1[0], t1[1], t1[2], t1[3]);
    }

    {
        #pragma unroll
        for (int nb = 0; nb < 4; nb++) {
            size_t base = ((size_t)(b0 + nb) * 1024 + p) * 64 + g * 12;
            *(uint2*)(YB + base) = make_uint2(pk[0][nb], pk[1][nb]);
            *(uint2*)(YB + base + 4) = make_uint2(pk[2][nb], pk[3][nb]);
            *(uint2*)(YB + base + 8) = make_uint2(pk[4][nb], pk[5][nb]);
        }
    }

    #pragma unroll
    for (int nb = 0; nb < 4; nb++) ld[nb] = wred(ld[nb]);
    __syncthreads();
    float* red = S;
    if ((tid & 31) == 0) {
        int w = tid >> 5;
        red[w * 4 + 0] = ld[0];
        red[w * 4 + 1] = ld[1];
        red[w * 4 + 2] = ld[2];
        red[w * 4 + 3] = ld[3];
    }
    __syncthreads();
    if (tid < 4) {
        float s = 0.f;
        #pragma unroll
        for (int w = 0; w < 8; w++) s += red[w * 4 + tid];
        atomicAdd(&g_tld[b0 + tid], s);
    }
}

// ---------------- layer 1: HMMA, single-stage smem (act halo + ALL weights) ---
#define L1_WT_BASE 40960
#define L1_SMEM 114688

__global__ void __launch_bounds__(256, 2)
l1_mma(const __nv_bfloat16* __restrict__ ag, const float* __restrict__ x1p,
       const float* __restrict__ cb, const float* __restrict__ ab,
       const float* __restrict__ als,
       __nv_bfloat16* __restrict__ xg, float* __restrict__ xf) {
    extern __shared__ char smc[];
    __shared__ float sE[48], sAb[48], red[8];
    uint32_t smem_base = smem_u32(smc);
    const int tid = threadIdx.x;
    const int lane = tid & 31, wid = tid >> 5;
    const int b = blockIdx.x;
    const int mt0 = blockIdx.y * 256;
    const int ytile0 = mt0 >> 5;
    const int m0 = (wid & 3) * 64;
    const int n0 = (wid >> 2) * 32;
    const int bq = b >> 2, nb = b & 3;

    if (tid < 48) {
        sE[tid] = expf(als[tid]);
        sAb[tid] = ab[tid];
    }

    // stage act halo: 320 rows
    for (int r = tid; r < 320; r += 256) {
        int yrel = r >> 5, x = r & 31;
        int yg = (ytile0 - 1 + yrel) & 31;
        const char* src = (const char*)(ag + ((size_t)b * 1024 + yg * 32 + x) * 64);
        #pragma unroll
        for (int s = 0; s < 8; s++) {
            uint32_t off = (uint32_t)r * 128 + s * 16;
            cpasync16(smem_base + swz(off), src + s * 16);
        }
    }
    // stage ALL weights: 576 rows
    for (int r = tid; r < 576; r += 256) {
        const char* src = (const char*)(g_w1 + (size_t)r * 64);
        #pragma unroll
        for (int s = 0; s < 8; s++) {
            uint32_t off = (uint32_t)r * 128 + s * 16;
            cpasync16(smem_base + L1_WT_BASE + swz(off), src + s * 16);
        }
    }
    cpasync_commit();

    float d[4][4][4];
    #pragma unroll
    for (int mt = 0; mt < 4; mt++)
        #pragma unroll
        for (int nt = 0; nt < 4; nt++)
            #pragma unroll
            for (int r = 0; r < 4; r++) d[mt][nt][r] = 0.f;

    int ply[4], plx[4];
    #pragma unroll
    for (int mt = 0; mt < 4; mt++) {
        int pl = m0 + mt * 16 + (lane & 15);
        ply[mt] = pl >> 5;
        plx[mt] = pl & 31;
    }

    cpasync_wait<0>();
    __syncthreads();

    #pragma unroll 1
    for (int c = 0; c < 9; c++) {
        int dy = c / 3 - 1, dx = c % 3 - 1;
        #pragma unroll
        for (int ks = 0; ks < 4; ks++) {
            uint32_t a[4][4];
            #pragma unroll
            for (int mt = 0; mt < 4; mt++) {
                int row = (ply[mt] + 1 + dy) * 32 + ((plx[mt] + dx) & 31);
                uint32_t off = (uint32_t)row * 128 + ks * 32 + (lane >> 4) * 16;
                ldsm4(a[mt], smem_base + swz(off));
            }
            uint32_t bf[2][4];
            #pragma unroll
            for (int nh = 0; nh < 2; nh++) {
                uint32_t row = c * 64 + n0 + nh * 16 + (lane & 7) + ((lane >> 4) << 3);
                uint32_t off = row * 128 + ks * 32 + ((lane >> 3) & 1) * 16;
                ldsm4(bf[nh], smem_base + L1_WT_BASE + swz(off));
            }
            #pragma unroll
            for (int mt = 0; mt < 4; mt++)
                #pragma unroll
                for (int nt = 0; nt < 4; nt++)
                    mma16816(d[mt][nt], a[mt], &bf[nt >> 1][(nt & 1) * 2]);
        }
    }

    // epilogue: center add (squeezed-co x1sq, direct index) + cb + actnorm + tanh
    float ldsum = 0.f;
    #pragma unroll
    for (int nt = 0; nt < 4; nt++) {
        int co = n0 + nt * 8 + (lane & 3) * 2;
        if (co < 48) {
            float e0 = sE[co], e1 = sE[co + 1];
            float ab0 = sAb[co], ab1 = sAb[co + 1];
            const float* xc0p = x1p + ((size_t)bq * 48 + co) * 4096 + nb;
            const float* xc1p = x1p + ((size_t)bq * 48 + co + 1) * 4096 + nb;
            #pragma unroll
            for (int mt = 0; mt < 4; mt++) {
                #pragma unroll
                for (int half = 0; half < 2; half++) {
                    int p = mt0 + m0 + mt * 16 + (lane >> 2) + half * 8;
                    float xc0 = xc0p[p * 4];
                    float xc1 = xc1p[p * 4];
                    float z0 = d[mt][nt][half * 2] + xc0 + cb[(size_t)co * 1024 + p];
                    float z1 = d[mt][nt][half * 2 + 1] + xc1 + cb[(size_t)(co + 1) * 1024 + p];
                    float t0 = tanhf(z0 * e0 + ab0);
                    float t1 = tanhf(z1 * e1 + ab1);
                    ldsum += log1pf(-t0 * t0) + log1pf(-t1 * t1);
                    int i = p >> 5, j = p & 31;
                    int y = i >> 1, x = j >> 1;
                    int hs = i & 1, ws = j & 1;
                    int g = (hs == ws) ? hs : (2 + hs);
                    size_t xi = ((size_t)b * 256 + y * 16 + x) * 192 + g * 48 + co;
                    __nv_bfloat162 pk2;
                    pk2.x = __float2bfloat16(t0);
                    pk2.y = __float2bfloat16(t1);
                    *(__nv_bfloat162*)(xg + xi) = pk2;
                    *(float2*)(xf + xi) = make_float2(t0, t1);
                }
            }
        }
    }
    ldsum = wred(ldsum);
    if (lane == 0) red[wid] = ldsum;
    __syncthreads();
    if (tid == 0) {
        float s = 0.f;
        #pragma unroll
        for (int w = 0; w < 8; w++) s += red[w];
        atomicAdd(&g_tld[b], s);
    }
}

// ---------------- layer 2: HMMA, act slabs once + dbuf weights, 1 sync/chunk --
#define L2_WT_BASE 98304
#define L2_SMEM 114688

__device__ __forceinline__ void l2_stage_wt(uint32_t smem_base, int buf, int c,
                                            int co0, int tid) {
    const char* wbase = (const char*)(g_w2 + ((size_t)c * 192 + co0) * 64);
    uint32_t ra = smem_base + L2_WT_BASE + buf * 8192;
    #pragma unroll
    for (int s2 = tid; s2 < 512; s2 += 256) {
        uint32_t off = (uint32_t)s2 * 16;
        cpasync16(ra + swz(off), wbase + off);
    }
    cpasync_commit();
}

__global__ void __launch_bounds__(256, 2)
l2_mma(const __nv_bfloat16* __restrict__ xg, const float* __restrict__ xf,
       const float* __restrict__ cb, const float* __restrict__ ab,
       const float* __restrict__ als, float* __restrict__ out) {
    extern __shared__ char smc[];
    __shared__ float sE[64], sAb[64];
    uint32_t smem_base = smem_u32(smc);
    const int tid = threadIdx.x;
    const int lane = tid & 31, wid = tid >> 5;
    const int b = blockIdx.x;
    const int co0 = blockIdx.y * 64;
    const int m0 = (wid & 3) * 64;
    const int n0 = (wid >> 2) * 32;

    if (tid < 64) {
        sE[tid] = expf(als[co0 + tid]);
        sAb[tid] = ab[co0 + tid];
    }

    // stage ALL 3 act slabs (768 rows) + first weight chunk, one group
    for (int r = tid; r < 768; r += 256) {
        int cc = r >> 8, p = r & 255;
        const char* src = (const char*)(xg + ((size_t)b * 256 + p) * 192 + cc * 64);
        uint32_t base = smem_base + cc * 32768;
        #pragma unroll
        for (int s = 0; s < 8; s++) {
            uint32_t off = (uint32_t)p * 128 + s * 16;
            cpasync16(base + swz(off), src + s * 16);
        }
    }
    l2_stage_wt(smem_base, 0, 0, co0, tid);  // commits the group

    float d[4][4][4];
    #pragma unroll
    for (int mt = 0; mt < 4; mt++)
        #pragma unroll
        for (int nt = 0; nt < 4; nt++)
            #pragma unroll
            for (int r = 0; r < 4; r++) d[mt][nt][r] = 0.f;

    int ply[4], plx[4];
    #pragma unroll
    for (int mt = 0; mt < 4; mt++) {
        int pl = m0 + mt * 16 + (lane & 15);
        ply[mt] = pl >> 4;
        plx[mt] = pl & 15;
    }

    #pragma unroll 1
    for (int c = 0; c < 27; c++) {
        int cur = c & 1;
        cpasync_wait<0>();
        __syncthreads();
        if (c + 1 < 27) l2_stage_wt(smem_base, 1 - cur, c + 1, co0, tid);
        int tap = c / 3, cc = c - tap * 3;
        int dy = tap / 3 - 1, dx = tap % 3 - 1;
        uint32_t actb = smem_base + cc * 32768;
        uint32_t wtb = smem_base + L2_WT_BASE + cur * 8192;
        #pragma unroll
        for (int ks = 0; ks < 4; ks++) {
            uint32_t a[4][4];
            #pragma unroll
            for (int mt = 0; mt < 4; mt++) {
                int row = ((ply[mt] + dy) & 15) * 16 + ((plx[mt] + dx) & 15);
                uint32_t off = (uint32_t)row * 128 + ks * 32 + (lane >> 4) * 16;
                ldsm4(a[mt], actb + swz(off));
            }
            uint32_t bf[2][4];
            #pragma unroll
            for (int nh = 0; nh < 2; nh++) {
                uint32_t row = n0 + nh * 16 + (lane & 7) + ((lane >> 4) << 3);
                uint32_t off = row * 128 + ks * 32 + ((lane >> 3) & 1) * 16;
                ldsm4(bf[nh], wtb + swz(off));
            }
            #pragma unroll
            for (int mt = 0; mt < 4; mt++)
                #pragma unroll
                for (int nt = 0; nt < 4; nt++)
                    mma16816(d[mt][nt], a[mt], &bf[nt >> 1][(nt & 1) * 2]);
        }
    }

    #pragma unroll
    for (int nt = 0; nt < 4; nt++) {
        int cr = n0 + nt * 8 + (lane & 3) * 2;
        int co = co0 + cr;
        float e0 = sE[cr], e1 = sE[cr + 1];
        float ab0 = sAb[cr], ab1 = sAb[cr + 1];
        const float* cb0p = cb + (size_t)co * 256;
        const float* cb1p = cb + (size_t)(co + 1) * 256;
        float* o0p = out + ((size_t)b * 192 + co) * 256;
        float* o1p = out + ((size_t)b * 192 + co + 1) * 256;
        #pragma unroll
        for (int mt = 0; mt < 4; mt++) {
            int p = m0 + mt * 16 + (lane >> 2);
            const float* xf0 = xf + ((size_t)b * 256 + p) * 192;
            const float* xf8 = xf + ((size_t)b * 256 + p + 8) * 192;
            o0p[p] = (d[mt][nt][0] + xf0[co] + cb0p[p]) * e0 + ab0;
            o1p[p] = (d[mt][nt][1] + xf0[co + 1] + cb1p[p]) * e1 + ab1;
            o0p[p + 8] = (d[mt][nt][2] + xf8[co] + cb0p[p + 8]) * e0 + ab0;
            o1p[p + 8] = (d[mt][nt][3] + xf8[co + 1] + cb1p[p + 8]) * e1 + ab1;
        }
    }
}

// ---------------- launch ----------------
extern "C" void kernel_launch(void* const* d_in, const int* in_sizes, int n_in,
                              void* d_out, int out_size) {
    const float* x = (const float*)d_in[0];
    const float* k0 = (const float*)d_in[1];
    const float* cb0 = (const float*)d_in[2];
    const float* ab0 = (const float*)d_in[3];
    const float* als0 = (const float*)d_in[4];
    const float* k1 = (const float*)d_in[5];
    const float* cb1 = (const float*)d_in[6];
    const float* ab1 = (const float*)d_in[7];
    const float* als1 = (const float*)d_in[8];
    const float* k2 = (const float*)d_in[9];
    const float* cb2 = (const float*)d_in[10];
    const float* ab2 = (const float*)d_in[11];
    const float* als2 = (const float*)d_in[12];
    float* out = (float*)d_out;

    float *x1, *xf;
    __nv_bfloat16 *ag1, *xg;
    cudaGetSymbolAddress((void**)&x1, g_x1);
    cudaGetSymbolAddress((void**)&ag1, g_ag1);
    cudaGetSymbolAddress((void**)&xg, g_xg);
    cudaGetSymbolAddress((void**)&xf, g_xf32);

    const int SM0 = 12 * 324 * 4 * 4 + 12 * 9 * 12 * 8 + 12 * 2 * 4;
    cudaFuncSetAttribute((const void*)conv_layer0,
                         cudaFuncAttributeMaxDynamicSharedMemorySize, SM0);
    cudaFuncSetAttribute((const void*)l1_mma,
                         cudaFuncAttributeMaxDynamicSharedMemorySize, L1_SMEM);
    cudaFuncSetAttribute((const void*)l2_mma,
                         cudaFuncAttributeMaxDynamicSharedMemorySize, L2_SMEM);

    // launch 1: fused setup (tld + ag1 pad + w1/w2 prep + kernel traces)
    setup_kernel<<<2483, 256>>>(k0, k1, k2);
    // launch 2: layer 0 FFMA conv
    conv_layer0<<<dim3(64, 16, 1), 256, SM0>>>(x, k0, cb0, ab0, als0, x1, ag1);
    // launch 3: layer 1 HMMA
    l1_mma<<<dim3(256, 4), 256, L1_SMEM>>>(ag1, x1, cb1, ab1, als1, xg, xf);
    // launch 4 (profiled slot): layer 2 HMMA
    l2_mma<<<dim3(256, 3), 256, L2_SMEM>>>(xg, xf, cb2, ab2, als2, out);
    // launch 5: finalize (freq sums + logdet outputs)
    fin_kernel<<<1, 256>>>(als0, als1, als2, out);
}